// round 9
// baseline (speedup 1.0000x reference)
#include <cuda_runtime.h>
#include <cuda_bf16.h>
#include <cstdint>

#define NPATH 8192
#define LMAX 32
#define DIN 256
#define EDIM 128
#define HDIM 128
#define G4 512
#define GRP 1024
#define RTOT (NPATH*LMAX)
#define LN_EPS 1e-5f

typedef unsigned long long ull;

// ---------------- device scratch (static, no allocation) ----------------
__device__ float g_gi[(size_t)RTOT*G4]; // 512 MB: x @ Wih^T + bih + bhh (valid t only)
__device__ float g_WhhT[HDIM*G4];       // Whh^T [k][j]
__device__ float g_h[NPATH*HDIM];
__device__ float g_logits[NPATH];
__device__ float g_e[NPATH];
__device__ unsigned g_gmax[GRP];
__device__ float g_gsum[GRP];
__device__ float g_cnt[GRP];
__device__ float g_wsum[GRP*HDIM];
__device__ int g_lcnt[40];
__device__ int g_lstart[40];
__device__ int g_perm[NPATH];
__device__ int g_nrows;
__device__ int g_rows[RTOT];

__device__ __forceinline__ float sigm(float x) { return 1.0f / (1.0f + expf(-x)); }

__device__ __forceinline__ unsigned enc_f(float f) {
    unsigned u = __float_as_uint(f);
    return (u & 0x80000000u) ? ~u : (u | 0x80000000u);
}
__device__ __forceinline__ float dec_f(unsigned k) {
    return (k & 0x80000000u) ? __uint_as_float(k ^ 0x80000000u) : __uint_as_float(~k);
}

// ---------------- packed f32x2 helpers ----------------
__device__ __forceinline__ ull fma2(ull a, ull b, ull c) {
    ull d;
    asm("fma.rn.f32x2 %0, %1, %2, %3;" : "=l"(d) : "l"(a), "l"(b), "l"(c));
    return d;
}
__device__ __forceinline__ ull pack2(float x, float y) {
    ull d;
    asm("mov.b64 %0, {%1, %2};" : "=l"(d) : "f"(x), "f"(y));
    return d;
}
__device__ __forceinline__ float2 unpack2(ull v) {
    float2 r;
    asm("mov.b64 {%0, %1}, %2;" : "=f"(r.x), "=f"(r.y) : "l"(v));
    return r;
}

// ---------------- sort kernels (counting sort by length, descending) ----------------
__global__ void k_hist(const int* __restrict__ lens) {
    int n = blockIdx.x * 256 + threadIdx.x;
    if (n < NPATH) atomicAdd(&g_lcnt[lens[n]], 1);
}
__global__ void k_scan() {
    if (threadIdx.x == 0 && blockIdx.x == 0) {
        int run = 0;
        for (int l = LMAX; l >= 1; l--) { g_lstart[l] = run; run += g_lcnt[l]; }
    }
}
__global__ void k_scatter(const int* __restrict__ lens) {
    int n = blockIdx.x * 256 + threadIdx.x;
    if (n < NPATH) {
        int pos = atomicAdd(&g_lstart[lens[n]], 1);
        g_perm[pos] = n;
    }
}
// packed valid-row list: g_rows[i] = path*32 + t for every valid (path,t)
__global__ void k_rowlist(const int* __restrict__ lens) {
    int n = blockIdx.x * 256 + threadIdx.x;
    if (n < NPATH) {
        int l = lens[n];
        int pos = atomicAdd(&g_nrows, l);
        int base = n * LMAX;
        for (int t = 0; t < l; t++) g_rows[pos + t] = base + t;
    }
}

// ---------------- kernel 0: transpose Whh once ----------------
__global__ void __launch_bounds__(256) k_tw(const float* __restrict__ Whh) {
    int idx = blockIdx.x * 256 + threadIdx.x;   // 65536 total
    int j = idx >> 7, k = idx & 127;
    g_WhhT[k * G4 + j] = Whh[j * HDIM + k];
}

// ---------------- kernel 1: fused projection+LN+tanh + input-gate GEMM ----------------
// block = 64 PACKED valid rows. Phase-2 A operands via dup-transposed Xd (no packs).
__global__ void __launch_bounds__(256, 2) k_fp(const float* __restrict__ inp,
                                               const float* __restrict__ W_in,
                                               const float* __restrict__ gamma,
                                               const float* __restrict__ beta,
                                               const float* __restrict__ Wih,
                                               const float* __restrict__ bih,
                                               const float* __restrict__ bhh) {
    extern __shared__ float sm[];
    float* Ad = sm;                  // 32 kk * 132 (dup pairs) = 4224
    float* Bs = sm + 4224;           // 32*132 = 4224
    float* Xd = sm + 8448;           // 128 k * 132 (dup pairs, 128 used) = 16896
    __shared__ int srow[64];         // total 25344 fl = 101376 B

    const int tid = threadIdx.x;
    const int tx = tid & 15, ty = tid >> 4;
    const int base = blockIdx.x * 64;
    const int nrows = g_nrows;
    if (base >= nrows) return;

    if (tid < 64) srow[tid] = (base + tid < nrows) ? g_rows[base + tid] : g_rows[base];
    __syncthreads();

    // ---- phase 1: x = tanh(LN(inp @ W_in^T)) ----
    ull acc[4][4];
#pragma unroll
    for (int i = 0; i < 4; i++)
#pragma unroll
        for (int j = 0; j < 4; j++) acc[i][j] = 0ull;

    for (int kt = 0; kt < 8; kt++) {
        __syncthreads();
        const int kb = kt * 32;
#pragma unroll
        for (int s = 0; s < 8; s++) {
            int idx = tid + s * 256;
            int kk = idx & 31, r = idx >> 5;
            float v = inp[(size_t)srow[r] * DIN + kb + kk];
            *(float2*)&Ad[kk * 132 + 2 * r] = make_float2(v, v);
        }
#pragma unroll
        for (int s = 0; s < 16; s++) {
            int idx = tid + s * 256;
            int kk = idx & 31, e = idx >> 5;
            Bs[kk * 132 + e] = W_in[e * DIN + kb + kk];
        }
        __syncthreads();
#pragma unroll 8
        for (int kk = 0; kk < 32; kk++) {
            ulonglong2 a01 = *(const ulonglong2*)&Ad[kk * 132 + 8 * ty];
            ulonglong2 a23 = *(const ulonglong2*)&Ad[kk * 132 + 8 * ty + 4];
            ull A2[4] = {a01.x, a01.y, a23.x, a23.y};
            ulonglong2 b01 = *(const ulonglong2*)&Bs[kk * 132 + tx * 8];
            ulonglong2 b23 = *(const ulonglong2*)&Bs[kk * 132 + tx * 8 + 4];
#pragma unroll
            for (int i = 0; i < 4; i++) {
                acc[i][0] = fma2(A2[i], b01.x, acc[i][0]);
                acc[i][1] = fma2(A2[i], b01.y, acc[i][1]);
                acc[i][2] = fma2(A2[i], b23.x, acc[i][2]);
                acc[i][3] = fma2(A2[i], b23.y, acc[i][3]);
            }
        }
    }
    __syncthreads();

    // ---- LN + tanh epilogue: write dup-transposed Xd[k][2r] = (x, x) ----
    {
        float gam[8], bet[8];
#pragma unroll
        for (int j = 0; j < 8; j++) { gam[j] = gamma[tx * 8 + j]; bet[j] = beta[tx * 8 + j]; }
#pragma unroll
        for (int i = 0; i < 4; i++) {
            float v[8];
#pragma unroll
            for (int p = 0; p < 4; p++) {
                float2 u = unpack2(acc[i][p]);
                v[2 * p] = u.x; v[2 * p + 1] = u.y;
            }
            float s = 0.0f, q = 0.0f;
#pragma unroll
            for (int j = 0; j < 8; j++) { s += v[j]; q += v[j] * v[j]; }
#pragma unroll
            for (int m = 8; m >= 1; m >>= 1) {
                s += __shfl_xor_sync(0xffffffffu, s, m);
                q += __shfl_xor_sync(0xffffffffu, q, m);
            }
            float mu = s * (1.0f / 128.0f);
            float var = q * (1.0f / 128.0f) - mu * mu;
            float rs = rsqrtf(var + LN_EPS);
            int r = ty * 4 + i;
#pragma unroll
            for (int j = 0; j < 8; j++) {
                float o = tanhf((v[j] - mu) * rs * gam[j] + bet[j]);
                *(float2*)&Xd[(tx * 8 + j) * 132 + 2 * r] = make_float2(o, o);
            }
        }
    }

    // ---- phase 2: gi = X @ Wih^T + b (A from Xd as dup pairs) ----
    for (int j0t = 0; j0t < 4; j0t++) {
        const int j0 = j0t * 128;
        ull acc2[4][4];
#pragma unroll
        for (int i = 0; i < 4; i++)
#pragma unroll
            for (int j = 0; j < 4; j++) acc2[i][j] = 0ull;

        for (int kt = 0; kt < 4; kt++) {
            __syncthreads();
            const int kb = kt * 32;
#pragma unroll
            for (int s = 0; s < 16; s++) {
                int idx = tid + s * 256;
                int kk = idx & 31, j = idx >> 5;
                Bs[kk * 132 + j] = Wih[(j0 + j) * HDIM + kb + kk];
            }
            __syncthreads();
#pragma unroll 8
            for (int kk = 0; kk < 32; kk++) {
                ulonglong2 a01 = *(const ulonglong2*)&Xd[(kb + kk) * 132 + 8 * ty];
                ulonglong2 a23 = *(const ulonglong2*)&Xd[(kb + kk) * 132 + 8 * ty + 4];
                ull A2[4] = {a01.x, a01.y, a23.x, a23.y};
                ulonglong2 b01 = *(const ulonglong2*)&Bs[kk * 132 + tx * 8];
                ulonglong2 b23 = *(const ulonglong2*)&Bs[kk * 132 + tx * 8 + 4];
#pragma unroll
                for (int i = 0; i < 4; i++) {
                    acc2[i][0] = fma2(A2[i], b01.x, acc2[i][0]);
                    acc2[i][1] = fma2(A2[i], b01.y, acc2[i][1]);
                    acc2[i][2] = fma2(A2[i], b23.x, acc2[i][2]);
                    acc2[i][3] = fma2(A2[i], b23.y, acc2[i][3]);
                }
            }
        }
        {
            float bs[8];
#pragma unroll
            for (int j = 0; j < 8; j++) {
                int jj = j0 + tx * 8 + j;
                bs[j] = bih[jj] + bhh[jj];
            }
#pragma unroll
            for (int i = 0; i < 4; i++) {
                int r = ty * 4 + i;
                if (base + r < nrows) {
                    float v[8];
#pragma unroll
                    for (int pp = 0; pp < 4; pp++) {
                        float2 u = unpack2(acc2[i][pp]);
                        v[2 * pp] = u.x; v[2 * pp + 1] = u.y;
                    }
                    size_t gbase = (size_t)srow[r] * G4 + j0 + tx * 8;
                    float4* dst = (float4*)&g_gi[gbase];
                    dst[0] = make_float4(v[0] + bs[0], v[1] + bs[1], v[2] + bs[2], v[3] + bs[3]);
                    dst[1] = make_float4(v[4] + bs[4], v[5] + bs[5], v[6] + bs[6], v[7] + bs[7]);
                }
            }
        }
    }
}

// ---------------- kernel 2: LSTM recurrence (sorted, balanced, dup-h) ----------------
__global__ void __launch_bounds__(256, 2) k_lstm(const int* __restrict__ lens) {
    extern __shared__ float sm[];
    float* hs = sm;                 // 128 * 68 = 8704 floats (dup-transposed)
    float* Bs = sm + 8704;          // 32 * 520 = 16640 -> total 25344 fl = 101376 B
    __shared__ int ln_s[32];
    __shared__ int sp[32];
    __shared__ int maxlen_s;

    const int tid = threadIdx.x;
    const int tx = tid & 31, ty = tid >> 5;
    const int bid = blockIdx.x;
    const int gidx = (bid < 148) ? bid : (403 - bid);
    const int n0 = gidx * 32;

#pragma unroll
    for (int s = 0; s < 34; s++) {
        int idx = tid + s * 256;
        if (idx < 8704) hs[idx] = 0.0f;
    }
    if (tid < 32) {
        int pid = g_perm[n0 + tid];
        sp[tid] = pid;
        int l = lens[pid];
        ln_s[tid] = l;
#pragma unroll
        for (int m = 16; m >= 1; m >>= 1) l = max(l, __shfl_xor_sync(0xffffffffu, l, m));
        if (tid == 0) maxlen_s = l;
    }
    __syncthreads();

    int myln[4];
    int pid4[4];
    int mymax = 0;
#pragma unroll
    for (int i = 0; i < 4; i++) {
        myln[i] = ln_s[4 * ty + i];
        pid4[i] = sp[4 * ty + i];
        mymax = max(mymax, myln[i]);
    }
    const int blkmax = maxlen_s;

    float c[4][4];
#pragma unroll
    for (int i = 0; i < 4; i++)
#pragma unroll
        for (int j = 0; j < 4; j++) c[i][j] = 0.0f;

    for (int t = 0; t < blkmax; t++) {
        ull acc[4][4][2];
#pragma unroll
        for (int i = 0; i < 4; i++)
#pragma unroll
            for (int q = 0; q < 4; q++) { acc[i][q][0] = 0ull; acc[i][q][1] = 0ull; }

        const bool active = (t < mymax);

        for (int kt = 0; kt < 4; kt++) {
            __syncthreads();
#pragma unroll
            for (int s = 0; s < 16; s++) {
                int f4 = tid + s * 256;
                int kk = f4 >> 7;
                int col = (f4 & 127) * 4;
                *(float4*)&Bs[kk * 520 + col] =
                    *(const float4*)&g_WhhT[(kt * 32 + kk) * G4 + col];
            }
            __syncthreads();
            if (active) {
                const int kb = kt * 32;
#pragma unroll 8
                for (int kk = 0; kk < 32; kk++) {
                    ulonglong2 a01 = *(const ulonglong2*)&hs[(kb + kk) * 68 + 8 * ty];
                    ulonglong2 a23 = *(const ulonglong2*)&hs[(kb + kk) * 68 + 8 * ty + 4];
                    ull A2[4] = {a01.x, a01.y, a23.x, a23.y};
#pragma unroll
                    for (int q = 0; q < 4; q++) {
                        ulonglong2 b = *(const ulonglong2*)&Bs[kk * 520 + q * 128 + tx * 4];
#pragma unroll
                        for (int i = 0; i < 4; i++) {
                            acc[i][q][0] = fma2(A2[i], b.x, acc[i][q][0]);
                            acc[i][q][1] = fma2(A2[i], b.y, acc[i][q][1]);
                        }
                    }
                }
            }
        }

        if (active) {
#pragma unroll
            for (int i = 0; i < 4; i++) {
                if (t < myln[i]) {
                    int n = 4 * ty + i;
                    size_t base = ((size_t)pid4[i] * LMAX + t) * G4 + tx * 4;
                    float4 gi = *(const float4*)&g_gi[base];
                    float4 gf = *(const float4*)&g_gi[base + 128];
                    float4 gg = *(const float4*)&g_gi[base + 256];
                    float4 go = *(const float4*)&g_gi[base + 384];
                    float2 i0 = unpack2(acc[i][0][0]), i1 = unpack2(acc[i][0][1]);
                    float2 f0 = unpack2(acc[i][1][0]), f1 = unpack2(acc[i][1][1]);
                    float2 g0 = unpack2(acc[i][2][0]), g1 = unpack2(acc[i][2][1]);
                    float2 o0 = unpack2(acc[i][3][0]), o1 = unpack2(acc[i][3][1]);
                    float xi[4] = {gi.x + i0.x, gi.y + i0.y, gi.z + i1.x, gi.w + i1.y};
                    float xf[4] = {gf.x + f0.x, gf.y + f0.y, gf.z + f1.x, gf.w + f1.y};
                    float xg[4] = {gg.x + g0.x, gg.y + g0.y, gg.z + g1.x, gg.w + g1.y};
                    float xo[4] = {go.x + o0.x, go.y + o0.y, go.z + o1.x, go.w + o1.y};
#pragma unroll
                    for (int j = 0; j < 4; j++) {
                        float cn = sigm(xf[j]) * c[i][j] + sigm(xi[j]) * tanhf(xg[j]);
                        c[i][j] = cn;
                        float h = sigm(xo[j]) * tanhf(cn);
                        *(float2*)&hs[(tx * 4 + j) * 68 + 2 * n] = make_float2(h, h);
                    }
                }
            }
        }
        __syncthreads();
    }

#pragma unroll
    for (int s = 0; s < 16; s++) {
        int idx = tid + s * 256;
        int n = idx >> 7, k = idx & 127;
        g_h[(size_t)sp[n] * HDIM + k] = hs[k * 68 + 2 * n];
    }
}

// ---------------- kernel 3a: init accumulators (+ counters) ----------------
__global__ void k_init() {
    int i = blockIdx.x * blockDim.x + threadIdx.x;
    if (i < GRP * HDIM) g_wsum[i] = 0.0f;
    if (i < GRP) {
        g_gsum[i] = 0.0f;
        g_cnt[i] = 0.0f;
        g_gmax[i] = 0u;
    }
    if (i < 40) g_lcnt[i] = 0;
    if (i == 0) g_nrows = 0;
}

// ---------------- kernel 3b: attention logits + segment max ----------------
__global__ void __launch_bounds__(256) k_logits(const float* __restrict__ ap,
                                                const int* __restrict__ seg) {
    int w = threadIdx.x >> 5, lane = threadIdx.x & 31;
    int n = blockIdx.x * 8 + w;
    float s = 0.0f;
#pragma unroll
    for (int q = 0; q < 4; q++) s += g_h[n * HDIM + lane + 32 * q] * ap[lane + 32 * q];
#pragma unroll
    for (int m = 16; m >= 1; m >>= 1) s += __shfl_xor_sync(0xffffffffu, s, m);
    if (lane == 0) {
        g_logits[n] = s;
        atomicMax(&g_gmax[seg[n]], enc_f(s));
    }
}

// ---------------- kernel 3c: exp + segment sum + count ----------------
__global__ void __launch_bounds__(256) k_expsum(const int* __restrict__ seg) {
    int n = blockIdx.x * 256 + threadIdx.x;
    int g = seg[n];
    float e = expf(g_logits[n] - dec_f(g_gmax[g]));
    g_e[n] = e;
    atomicAdd(&g_gsum[g], e);
    atomicAdd(&g_cnt[g], 1.0f);
}

// ---------------- kernel 3d: weighted hidden sum per group ----------------
__global__ void __launch_bounds__(256) k_wsum(const int* __restrict__ seg) {
    int w = threadIdx.x >> 5, lane = threadIdx.x & 31;
    int n = blockIdx.x * 8 + w;
    float e = g_e[n];
    int g = seg[n];
#pragma unroll
    for (int q = 0; q < 4; q++)
        atomicAdd(&g_wsum[g * HDIM + lane + 32 * q], e * g_h[n * HDIM + lane + 32 * q]);
}

// ---------------- kernel 4: head ----------------
__global__ void __launch_bounds__(256) k_head(const float* __restrict__ W_out,
                                              const float* __restrict__ W_cls,
                                              const float* __restrict__ ap,
                                              float* __restrict__ out,
                                              int out_size) {
    __shared__ float cs[16 * 128];
    __shared__ float cvs[16 * 128];
    const int tid = threadIdx.x;
    const int g0 = blockIdx.x * 16;
    const bool full = (out_size >= 2048 + GRP * HDIM + HDIM);

#pragma unroll
    for (int s = 0; s < 8; s++) {
        int idx = tid + s * 256;
        int gg = idx >> 7, k = idx & 127;
        int gi = g0 + gg;
        cs[gg * 128 + k] = g_wsum[gi * HDIM + k] / (g_gsum[gi] * g_cnt[gi]);
    }
    __syncthreads();

    int row = tid >> 4;
    int c0 = (tid & 15) * 8;
    float acc[8];
#pragma unroll
    for (int j = 0; j < 8; j++) acc[j] = 0.0f;
    for (int k = 0; k < 128; k++) {
        float a = cs[row * 128 + k];
#pragma unroll
        for (int j = 0; j < 8; j++) acc[j] += a * W_out[(c0 + j) * 128 + k];
    }
#pragma unroll
    for (int j = 0; j < 8; j++) {
        cvs[row * 128 + c0 + j] = acc[j];
        if (full) out[2048 + (g0 + row) * 128 + c0 + j] = acc[j];
    }
    __syncthreads();

    if (tid < 32) {
        int r = tid >> 1, c = tid & 1;
        float s = 0.0f;
        for (int k = 0; k < 128; k++) s += cvs[r * 128 + k] * W_cls[c * 128 + k];
        out[(g0 + r) * 2 + c] = s;
    }
    if (full && blockIdx.x == 0 && tid < 128) out[2048 + GRP * HDIM + tid] = ap[tid];
}

// ---------------- launch ----------------
extern "C" void kernel_launch(void* const* d_in, const int* in_sizes, int n_in,
                              void* d_out, int out_size) {
    const float* inputs = (const float*)d_in[0];
    const int* lens     = (const int*)d_in[1];
    const int* seg      = (const int*)d_in[2];
    const float* W_in   = (const float*)d_in[3];
    const float* gamma  = (const float*)d_in[4];
    const float* beta   = (const float*)d_in[5];
    const float* Wih    = (const float*)d_in[6];
    const float* Whh    = (const float*)d_in[7];
    const float* bih    = (const float*)d_in[8];
    const float* bhh    = (const float*)d_in[9];
    const float* ap     = (const float*)d_in[10];
    const float* W_out  = (const float*)d_in[11];
    const float* W_cls  = (const float*)d_in[12];
    float* out = (float*)d_out;

    const int fp_smem   = 25344 * 4;   // 101376 B
    const int lstm_smem = 25344 * 4;   // 101376 B
    cudaFuncSetAttribute(k_fp, cudaFuncAttributeMaxDynamicSharedMemorySize, fp_smem);
    cudaFuncSetAttribute(k_lstm, cudaFuncAttributeMaxDynamicSharedMemorySize, lstm_smem);

    // k_fp is launch #6 so ncu (-s 5 -c 1) profiles it
    k_init<<<(GRP * HDIM + 255) / 256, 256>>>();
    k_hist<<<NPATH / 256, 256>>>(lens);
    k_scan<<<1, 32>>>();
    k_scatter<<<NPATH / 256, 256>>>(lens);
    k_rowlist<<<NPATH / 256, 256>>>(lens);
    k_fp<<<RTOT / 64, 256, fp_smem>>>(inputs, W_in, gamma, beta, Wih, bih, bhh);
    k_tw<<<256, 256>>>(Whh);
    k_lstm<<<NPATH / 32, 256, lstm_smem>>>(lens);
    k_logits<<<NPATH / 8, 256>>>(ap, seg);
    k_expsum<<<NPATH / 256, 256>>>(seg);
    k_wsum<<<NPATH / 8, 256>>>(seg);
    k_head<<<GRP / 16, 256>>>(W_out, W_cls, ap, out, out_size);
}

// round 10
// speedup vs baseline: 1.2932x; 1.2932x over previous
#include <cuda_runtime.h>
#include <cuda_bf16.h>
#include <cstdint>

#define NPATH 8192
#define LMAX 32
#define DIN 256
#define EDIM 128
#define HDIM 128
#define G4 512
#define GRP 1024
#define RTOT (NPATH*LMAX)
#define LN_EPS 1e-5f

typedef unsigned long long ull;

// ---------------- device scratch (static, no allocation) ----------------
__device__ float g_gi[(size_t)RTOT*G4]; // 512 MB
__device__ float g_WhhT[HDIM*G4];       // Whh^T [k][j]
__device__ __nv_bfloat16 g_WinH[EDIM*DIN];
__device__ __nv_bfloat16 g_WinL[EDIM*DIN];
__device__ __nv_bfloat16 g_WihH[G4*HDIM];
__device__ __nv_bfloat16 g_WihL[G4*HDIM];
__device__ float g_h[NPATH*HDIM];
__device__ float g_logits[NPATH];
__device__ float g_e[NPATH];
__device__ unsigned g_gmax[GRP];
__device__ float g_gsum[GRP];
__device__ float g_cnt[GRP];
__device__ float g_wsum[GRP*HDIM];
__device__ int g_lcnt[40];
__device__ int g_lstart[40];
__device__ int g_perm[NPATH];
__device__ int g_nrows;
__device__ int g_rows[RTOT];

__device__ __forceinline__ float sigm(float x) { return 1.0f / (1.0f + expf(-x)); }

__device__ __forceinline__ unsigned enc_f(float f) {
    unsigned u = __float_as_uint(f);
    return (u & 0x80000000u) ? ~u : (u | 0x80000000u);
}
__device__ __forceinline__ float dec_f(unsigned k) {
    return (k & 0x80000000u) ? __uint_as_float(k ^ 0x80000000u) : __uint_as_float(~k);
}

// ---------------- packed f32x2 helpers (k_lstm) ----------------
__device__ __forceinline__ ull fma2(ull a, ull b, ull c) {
    ull d;
    asm("fma.rn.f32x2 %0, %1, %2, %3;" : "=l"(d) : "l"(a), "l"(b), "l"(c));
    return d;
}
__device__ __forceinline__ float2 unpack2(ull v) {
    float2 r;
    asm("mov.b64 {%0, %1}, %2;" : "=f"(r.x), "=f"(r.y) : "l"(v));
    return r;
}

// ---------------- mma helper ----------------
#define MMA_BF16(Cr, a0, a1, a2, a3, b0, b1) \
    asm volatile("mma.sync.aligned.m16n8k16.row.col.f32.bf16.bf16.f32 " \
        "{%0,%1,%2,%3}, {%4,%5,%6,%7}, {%8,%9}, {%0,%1,%2,%3};" \
        : "+f"((Cr)[0]), "+f"((Cr)[1]), "+f"((Cr)[2]), "+f"((Cr)[3]) \
        : "r"(a0), "r"(a1), "r"(a2), "r"(a3), "r"(b0), "r"(b1))

// ---------------- sort kernels ----------------
__global__ void k_hist(const int* __restrict__ lens) {
    int n = blockIdx.x * 256 + threadIdx.x;
    if (n < NPATH) atomicAdd(&g_lcnt[lens[n]], 1);
}
__global__ void k_scan() {
    if (threadIdx.x == 0 && blockIdx.x == 0) {
        int run = 0;
        for (int l = LMAX; l >= 1; l--) { g_lstart[l] = run; run += g_lcnt[l]; }
    }
}
__global__ void k_scatter(const int* __restrict__ lens) {
    int n = blockIdx.x * 256 + threadIdx.x;
    if (n < NPATH) {
        int pos = atomicAdd(&g_lstart[lens[n]], 1);
        g_perm[pos] = n;
    }
}
__global__ void k_rowlist(const int* __restrict__ lens) {
    int n = blockIdx.x * 256 + threadIdx.x;
    if (n < NPATH) {
        int l = lens[n];
        int pos = atomicAdd(&g_nrows, l);
        int base = n * LMAX;
        for (int t = 0; t < l; t++) g_rows[pos + t] = base + t;
    }
}

// ---------------- kernel 0: transpose Whh + bf16-split W_in/Wih ----------------
__global__ void __launch_bounds__(256) k_prep(const float* __restrict__ Whh,
                                              const float* __restrict__ Wih,
                                              const float* __restrict__ W_in) {
    int idx = blockIdx.x * 256 + threadIdx.x;   // 65536 total
    {
        int j = idx >> 7, k = idx & 127;
        g_WhhT[k * G4 + j] = Whh[j * HDIM + k];
    }
    {
        float v = Wih[idx];
        __nv_bfloat16 h = __float2bfloat16(v);
        g_WihH[idx] = h;
        g_WihL[idx] = __float2bfloat16(v - __bfloat162float(h));
    }
    if (idx < EDIM * DIN) {
        float v = W_in[idx];
        __nv_bfloat16 h = __float2bfloat16(v);
        g_WinH[idx] = h;
        g_WinL[idx] = __float2bfloat16(v - __bfloat162float(h));
    }
}

// smem offsets (b32 units)
#define OFF_AH   0
#define OFF_AL   4608
#define OFF_XH   9216
#define OFF_XL   17920
#define OFF_RED  26624
#define OFF_GAM  27136
#define OFF_BET  27264
#define OFF_BIAS 27392
#define OFF_SROW 27904
#define FP_SMEM_B32 28032

// ---------------- kernel 1: mma-based fused projection+LN+tanh + gate GEMM ----------------
// 128 packed rows per block, 256 threads (8 warps = 4m x 2n), bf16x3 HMMA.
__global__ void __launch_bounds__(256, 2) k_fp(const float* __restrict__ inp,
                                               const float* __restrict__ gamma,
                                               const float* __restrict__ beta,
                                               const float* __restrict__ bih,
                                               const float* __restrict__ bhh) {
    extern __shared__ uint32_t s32[];
    __nv_bfloat16* Ah16 = (__nv_bfloat16*)(s32 + OFF_AH);   // [128][72] bf16 (36 b32 stride)
    __nv_bfloat16* Al16 = (__nv_bfloat16*)(s32 + OFF_AL);
    const uint32_t* Ah32 = s32 + OFF_AH;
    const uint32_t* Al32 = s32 + OFF_AL;
    __nv_bfloat162* Xh2 = (__nv_bfloat162*)(s32 + OFF_XH);  // [128][68] b32 stride
    __nv_bfloat162* Xl2 = (__nv_bfloat162*)(s32 + OFF_XL);
    const uint32_t* Xh32 = s32 + OFF_XH;
    const uint32_t* Xl32 = s32 + OFF_XL;
    float2* red = (float2*)(s32 + OFF_RED);                 // [128][2]
    float* sgam = (float*)(s32 + OFF_GAM);
    float* sbet = (float*)(s32 + OFF_BET);
    float* sbias = (float*)(s32 + OFF_BIAS);
    int* srow = (int*)(s32 + OFF_SROW);

    const int tid = threadIdx.x;
    const int lane = tid & 31, wid = tid >> 5;
    const int warp_m = wid & 3, warp_n = wid >> 2;
    const int r = lane >> 2, cq = lane & 3;
    const int base = blockIdx.x * 128;
    const int nrows = g_nrows;
    if (base >= nrows) return;

    if (tid < 128) {
        srow[tid] = (base + tid < nrows) ? g_rows[base + tid] : g_rows[base];
        sgam[tid] = gamma[tid];
        sbet[tid] = beta[tid];
    }
    sbias[tid] = bih[tid] + bhh[tid];
    sbias[tid + 256] = bih[tid + 256] + bhh[tid + 256];
    __syncthreads();

    // ================= phase 1: C = inp @ W_in^T (M=128, N=128, K=256) =================
    float C[2][8][4];
#pragma unroll
    for (int mt = 0; mt < 2; mt++)
#pragma unroll
        for (int nt = 0; nt < 8; nt++)
#pragma unroll
            for (int v = 0; v < 4; v++) C[mt][nt][v] = 0.0f;

    for (int ks = 0; ks < 4; ks++) {   // K staged in 4 chunks of 64
        __syncthreads();
#pragma unroll
        for (int s = 0; s < 32; s++) {
            int idx = tid + s * 256;
            int row = idx >> 6, c = idx & 63;
            float v = inp[(size_t)srow[row] * DIN + ks * 64 + c];
            __nv_bfloat16 h = __float2bfloat16(v);
            Ah16[row * 72 + c] = h;
            Al16[row * 72 + c] = __float2bfloat16(v - __bfloat162float(h));
        }
        __syncthreads();
#pragma unroll
        for (int k4 = 0; k4 < 4; k4++) {
            const int k8 = k4 * 8;
            uint32_t ah[2][4], al[2][4];
#pragma unroll
            for (int mt = 0; mt < 2; mt++) {
                int row = warp_m * 32 + mt * 16 + r;
                ah[mt][0] = Ah32[row * 36 + k8 + cq];
                ah[mt][1] = Ah32[(row + 8) * 36 + k8 + cq];
                ah[mt][2] = Ah32[row * 36 + k8 + cq + 4];
                ah[mt][3] = Ah32[(row + 8) * 36 + k8 + cq + 4];
                al[mt][0] = Al32[row * 36 + k8 + cq];
                al[mt][1] = Al32[(row + 8) * 36 + k8 + cq];
                al[mt][2] = Al32[row * 36 + k8 + cq + 4];
                al[mt][3] = Al32[(row + 8) * 36 + k8 + cq + 4];
            }
            const int kbg = ks * 64 + k4 * 16;
#pragma unroll
            for (int nt = 0; nt < 8; nt++) {
                int n = warp_n * 64 + nt * 8 + r;
                const uint32_t* Bh = (const uint32_t*)(g_WinH + n * DIN + kbg + 2 * cq);
                const uint32_t* Bl = (const uint32_t*)(g_WinL + n * DIN + kbg + 2 * cq);
                uint32_t bh0 = Bh[0], bh1 = Bh[4];
                uint32_t bl0 = Bl[0], bl1 = Bl[4];
#pragma unroll
                for (int mt = 0; mt < 2; mt++) {
                    MMA_BF16(C[mt][nt], ah[mt][0], ah[mt][1], ah[mt][2], ah[mt][3], bh0, bh1);
                    MMA_BF16(C[mt][nt], ah[mt][0], ah[mt][1], ah[mt][2], ah[mt][3], bl0, bl1);
                    MMA_BF16(C[mt][nt], al[mt][0], al[mt][1], al[mt][2], al[mt][3], bh0, bh1);
                }
            }
        }
    }

    // ================= LN + tanh epilogue -> Xh/Xl (bf16 split) =================
    __syncthreads();
#pragma unroll
    for (int mt = 0; mt < 2; mt++) {
        float sA = 0.f, qA = 0.f, sB = 0.f, qB = 0.f;
#pragma unroll
        for (int nt = 0; nt < 8; nt++) {
            sA += C[mt][nt][0] + C[mt][nt][1];
            qA += C[mt][nt][0] * C[mt][nt][0] + C[mt][nt][1] * C[mt][nt][1];
            sB += C[mt][nt][2] + C[mt][nt][3];
            qB += C[mt][nt][2] * C[mt][nt][2] + C[mt][nt][3] * C[mt][nt][3];
        }
#pragma unroll
        for (int m = 1; m <= 2; m <<= 1) {
            sA += __shfl_xor_sync(0xffffffffu, sA, m);
            qA += __shfl_xor_sync(0xffffffffu, qA, m);
            sB += __shfl_xor_sync(0xffffffffu, sB, m);
            qB += __shfl_xor_sync(0xffffffffu, qB, m);
        }
        if (cq == 0) {
            int rowA = warp_m * 32 + mt * 16 + r;
            red[rowA * 2 + warp_n] = make_float2(sA, qA);
            red[(rowA + 8) * 2 + warp_n] = make_float2(sB, qB);
        }
    }
    __syncthreads();

    float muv[2][2], rsv[2][2];
#pragma unroll
    for (int mt = 0; mt < 2; mt++)
#pragma unroll
        for (int hb = 0; hb < 2; hb++) {
            int row = warp_m * 32 + mt * 16 + r + hb * 8;
            float2 p0 = red[row * 2 + 0], p1 = red[row * 2 + 1];
            float s = p0.x + p1.x, q = p0.y + p1.y;
            float mu = s * (1.0f / 128.0f);
            float var = q * (1.0f / 128.0f) - mu * mu;
            muv[mt][hb] = mu;
            rsv[mt][hb] = rsqrtf(var + LN_EPS);
        }

#pragma unroll
    for (int mt = 0; mt < 2; mt++) {
#pragma unroll
        for (int nt = 0; nt < 8; nt++) {
            int col = warp_n * 64 + nt * 8 + 2 * cq;
            int c2 = warp_n * 32 + nt * 4 + cq;
            float g0 = sgam[col], g1 = sgam[col + 1];
            float b0 = sbet[col], b1 = sbet[col + 1];
            int rowA = warp_m * 32 + mt * 16 + r;
            {
                float x0 = tanhf((C[mt][nt][0] - muv[mt][0]) * rsv[mt][0] * g0 + b0);
                float x1 = tanhf((C[mt][nt][1] - muv[mt][0]) * rsv[mt][0] * g1 + b1);
                __nv_bfloat16 h0 = __float2bfloat16(x0);
                __nv_bfloat16 h1 = __float2bfloat16(x1);
                __nv_bfloat162 hv; hv.x = h0; hv.y = h1;
                __nv_bfloat162 lv;
                lv.x = __float2bfloat16(x0 - __bfloat162float(h0));
                lv.y = __float2bfloat16(x1 - __bfloat162float(h1));
                Xh2[rowA * 68 + c2] = hv;
                Xl2[rowA * 68 + c2] = lv;
            }
            {
                float x0 = tanhf((C[mt][nt][2] - muv[mt][1]) * rsv[mt][1] * g0 + b0);
                float x1 = tanhf((C[mt][nt][3] - muv[mt][1]) * rsv[mt][1] * g1 + b1);
                __nv_bfloat16 h0 = __float2bfloat16(x0);
                __nv_bfloat16 h1 = __float2bfloat16(x1);
                __nv_bfloat162 hv; hv.x = h0; hv.y = h1;
                __nv_bfloat162 lv;
                lv.x = __float2bfloat16(x0 - __bfloat162float(h0));
                lv.y = __float2bfloat16(x1 - __bfloat162float(h1));
                Xh2[(rowA + 8) * 68 + c2] = hv;
                Xl2[(rowA + 8) * 68 + c2] = lv;
            }
        }
    }
    __syncthreads();

    // ================= phase 2: gi = X @ Wih^T + b (M=128, N=512, K=128) =================
    for (int pass = 0; pass < 8; pass++) {
        float D[2][4][4];
#pragma unroll
        for (int mt = 0; mt < 2; mt++)
#pragma unroll
            for (int nt = 0; nt < 4; nt++)
#pragma unroll
                for (int v = 0; v < 4; v++) D[mt][nt][v] = 0.0f;

#pragma unroll
        for (int k = 0; k < 8; k++) {
            const int k8 = k * 8;
            uint32_t ah[2][4], al[2][4];
#pragma unroll
            for (int mt = 0; mt < 2; mt++) {
                int row = warp_m * 32 + mt * 16 + r;
                ah[mt][0] = Xh32[row * 68 + k8 + cq];
                ah[mt][1] = Xh32[(row + 8) * 68 + k8 + cq];
                ah[mt][2] = Xh32[row * 68 + k8 + cq + 4];
                ah[mt][3] = Xh32[(row + 8) * 68 + k8 + cq + 4];
                al[mt][0] = Xl32[row * 68 + k8 + cq];
                al[mt][1] = Xl32[(row + 8) * 68 + k8 + cq];
                al[mt][2] = Xl32[row * 68 + k8 + cq + 4];
                al[mt][3] = Xl32[(row + 8) * 68 + k8 + cq + 4];
            }
#pragma unroll
            for (int nt = 0; nt < 4; nt++) {
                int n = pass * 64 + warp_n * 32 + nt * 8 + r;
                const uint32_t* Bh = (const uint32_t*)(g_WihH + n * HDIM + k * 16 + 2 * cq);
                const uint32_t* Bl = (const uint32_t*)(g_WihL + n * HDIM + k * 16 + 2 * cq);
                uint32_t bh0 = Bh[0], bh1 = Bh[4];
                uint32_t bl0 = Bl[0], bl1 = Bl[4];
#pragma unroll
                for (int mt = 0; mt < 2; mt++) {
                    MMA_BF16(D[mt][nt], ah[mt][0], ah[mt][1], ah[mt][2], ah[mt][3], bh0, bh1);
                    MMA_BF16(D[mt][nt], ah[mt][0], ah[mt][1], ah[mt][2], ah[mt][3], bl0, bl1);
                    MMA_BF16(D[mt][nt], al[mt][0], al[mt][1], al[mt][2], al[mt][3], bh0, bh1);
                }
            }
        }
        // store with bias, masked
#pragma unroll
        for (int mt = 0; mt < 2; mt++) {
#pragma unroll
            for (int nt = 0; nt < 4; nt++) {
                int col = pass * 64 + warp_n * 32 + nt * 8 + 2 * cq;
                float2 bb = *(const float2*)&sbias[col];
                int rowA = warp_m * 32 + mt * 16 + r;
                if (base + rowA < nrows) {
                    float2 o = make_float2(D[mt][nt][0] + bb.x, D[mt][nt][1] + bb.y);
                    *(float2*)&g_gi[(size_t)srow[rowA] * G4 + col] = o;
                }
                int rowB = rowA + 8;
                if (base + rowB < nrows) {
                    float2 o = make_float2(D[mt][nt][2] + bb.x, D[mt][nt][3] + bb.y);
                    *(float2*)&g_gi[(size_t)srow[rowB] * G4 + col] = o;
                }
            }
        }
    }
}

// ---------------- kernel 2: LSTM recurrence (sorted, balanced, dup-h) — R8 version ----------------
__global__ void __launch_bounds__(256, 2) k_lstm(const int* __restrict__ lens) {
    extern __shared__ float sm[];
    float* hs = sm;                 // 128 * 68 = 8704 floats (dup-transposed)
    float* Bs = sm + 8704;          // 32 * 520 = 16640 -> total 25344 fl
    __shared__ int ln_s[32];
    __shared__ int sp[32];
    __shared__ int maxlen_s;

    const int tid = threadIdx.x;
    const int tx = tid & 31, ty = tid >> 5;
    const int bid = blockIdx.x;
    const int gidx = (bid < 148) ? bid : (403 - bid);
    const int n0 = gidx * 32;

#pragma unroll
    for (int s = 0; s < 34; s++) {
        int idx = tid + s * 256;
        if (idx < 8704) hs[idx] = 0.0f;
    }
    if (tid < 32) {
        int pid = g_perm[n0 + tid];
        sp[tid] = pid;
        int l = lens[pid];
        ln_s[tid] = l;
#pragma unroll
        for (int m = 16; m >= 1; m >>= 1) l = max(l, __shfl_xor_sync(0xffffffffu, l, m));
        if (tid == 0) maxlen_s = l;
    }
    __syncthreads();

    int myln[4];
    int pid4[4];
    int mymax = 0;
#pragma unroll
    for (int i = 0; i < 4; i++) {
        myln[i] = ln_s[4 * ty + i];
        pid4[i] = sp[4 * ty + i];
        mymax = max(mymax, myln[i]);
    }
    const int blkmax = maxlen_s;

    float c[4][4];
#pragma unroll
    for (int i = 0; i < 4; i++)
#pragma unroll
        for (int j = 0; j < 4; j++) c[i][j] = 0.0f;

    for (int t = 0; t < blkmax; t++) {
        ull acc[4][4][2];
#pragma unroll
        for (int i = 0; i < 4; i++)
#pragma unroll
            for (int q = 0; q < 4; q++) { acc[i][q][0] = 0ull; acc[i][q][1] = 0ull; }

        const bool active = (t < mymax);

        for (int kt = 0; kt < 4; kt++) {
            __syncthreads();
#pragma unroll
            for (int s = 0; s < 16; s++) {
                int f4 = tid + s * 256;
                int kk = f4 >> 7;
                int col = (f4 & 127) * 4;
                *(float4*)&Bs[kk * 520 + col] =
                    *(const float4*)&g_WhhT[(kt * 32 + kk) * G4 + col];
            }
            __syncthreads();
            if (active) {
                const int kb = kt * 32;
#pragma unroll 8
                for (int kk = 0; kk < 32; kk++) {
                    ulonglong2 a01 = *(const ulonglong2*)&hs[(kb + kk) * 68 + 8 * ty];
                    ulonglong2 a23 = *(const ulonglong2*)&hs[(kb + kk) * 68 + 8 * ty + 4];
                    ull A2[4] = {a01.x, a01.y, a23.x, a23.y};
#pragma unroll
                    for (int q = 0; q < 4; q++) {
                        ulonglong2 b = *(const ulonglong2*)&Bs[kk * 520 + q * 128 + tx * 4];
#pragma unroll
                        for (int i = 0; i < 4; i++) {
                            acc[i][q][0] = fma2(A2[i], b.x, acc[i][q][0]);
                            acc[i][q][1] = fma2(A2[i], b.y, acc[i][q][1]);
                        }
                    }
                }
            }
        }

        if (active) {
#pragma unroll
            for (int i = 0; i < 4; i++) {
                if (t < myln[i]) {
                    int n = 4 * ty + i;
                    size_t base = ((size_t)pid4[i] * LMAX + t) * G4 + tx * 4;
                    float4 gi = *(const float4*)&g_gi[base];
                    float4 gf = *(const float4*)&g_gi[base + 128];
                    float4 gg = *(const float4*)&g_gi[base + 256];
                    float4 go = *(const float4*)&g_gi[base + 384];
                    float2 i0 = unpack2(acc[i][0][0]), i1 = unpack2(acc[i][0][1]);
                    float2 f0 = unpack2(acc[i][1][0]), f1 = unpack2(acc[i][1][1]);
                    float2 g0 = unpack2(acc[i][2][0]), g1 = unpack2(acc[i][2][1]);
                    float2 o0 = unpack2(acc[i][3][0]), o1 = unpack2(acc[i][3][1]);
                    float xi[4] = {gi.x + i0.x, gi.y + i0.y, gi.z + i1.x, gi.w + i1.y};
                    float xf[4] = {gf.x + f0.x, gf.y + f0.y, gf.z + f1.x, gf.w + f1.y};
                    float xg[4] = {gg.x + g0.x, gg.y + g0.y, gg.z + g1.x, gg.w + g1.y};
                    float xo[4] = {go.x + o0.x, go.y + o0.y, go.z + o1.x, go.w + o1.y};
#pragma unroll
                    for (int j = 0; j < 4; j++) {
                        float cn = sigm(xf[j]) * c[i][j] + sigm(xi[j]) * tanhf(xg[j]);
                        c[i][j] = cn;
                        float h = sigm(xo[j]) * tanhf(cn);
                        *(float2*)&hs[(tx * 4 + j) * 68 + 2 * n] = make_float2(h, h);
                    }
                }
            }
        }
        __syncthreads();
    }

#pragma unroll
    for (int s = 0; s < 16; s++) {
        int idx = tid + s * 256;
        int n = idx >> 7, k = idx & 127;
        g_h[(size_t)sp[n] * HDIM + k] = hs[k * 68 + 2 * n];
    }
}

// ---------------- kernel 3a: init accumulators (+ counters) ----------------
__global__ void k_init() {
    int i = blockIdx.x * blockDim.x + threadIdx.x;
    if (i < GRP * HDIM) g_wsum[i] = 0.0f;
    if (i < GRP) {
        g_gsum[i] = 0.0f;
        g_cnt[i] = 0.0f;
        g_gmax[i] = 0u;
    }
    if (i < 40) g_lcnt[i] = 0;
    if (i == 0) g_nrows = 0;
}

// ---------------- kernel 3b: attention logits + segment max ----------------
__global__ void __launch_bounds__(256) k_logits(const float* __restrict__ ap,
                                                const int* __restrict__ seg) {
    int w = threadIdx.x >> 5, lane = threadIdx.x & 31;
    int n = blockIdx.x * 8 + w;
    float s = 0.0f;
#pragma unroll
    for (int q = 0; q < 4; q++) s += g_h[n * HDIM + lane + 32 * q] * ap[lane + 32 * q];
#pragma unroll
    for (int m = 16; m >= 1; m >>= 1) s += __shfl_xor_sync(0xffffffffu, s, m);
    if (lane == 0) {
        g_logits[n] = s;
        atomicMax(&g_gmax[seg[n]], enc_f(s));
    }
}

// ---------------- kernel 3c: exp + segment sum + count ----------------
__global__ void __launch_bounds__(256) k_expsum(const int* __restrict__ seg) {
    int n = blockIdx.x * 256 + threadIdx.x;
    int g = seg[n];
    float e = expf(g_logits[n] - dec_f(g_gmax[g]));
    g_e[n] = e;
    atomicAdd(&g_gsum[g], e);
    atomicAdd(&g_cnt[g], 1.0f);
}

// ---------------- kernel 3d: weighted hidden sum per group ----------------
__global__ void __launch_bounds__(256) k_wsum(const int* __restrict__ seg) {
    int w = threadIdx.x >> 5, lane = threadIdx.x & 31;
    int n = blockIdx.x * 8 + w;
    float e = g_e[n];
    int g = seg[n];
#pragma unroll
    for (int q = 0; q < 4; q++)
        atomicAdd(&g_wsum[g * HDIM + lane + 32 * q], e * g_h[n * HDIM + lane + 32 * q]);
}

// ---------------- kernel 4: head ----------------
__global__ void __launch_bounds__(256) k_head(const float* __restrict__ W_out,
                                              const float* __restrict__ W_cls,
                                              const float* __restrict__ ap,
                                              float* __restrict__ out,
                                              int out_size) {
    __shared__ float cs[16 * 128];
    __shared__ float cvs[16 * 128];
    const int tid = threadIdx.x;
    const int g0 = blockIdx.x * 16;
    const bool full = (out_size >= 2048 + GRP * HDIM + HDIM);

#pragma unroll
    for (int s = 0; s < 8; s++) {
        int idx = tid + s * 256;
        int gg = idx >> 7, k = idx & 127;
        int gi = g0 + gg;
        cs[gg * 128 + k] = g_wsum[gi * HDIM + k] / (g_gsum[gi] * g_cnt[gi]);
    }
    __syncthreads();

    int row = tid >> 4;
    int c0 = (tid & 15) * 8;
    float acc[8];
#pragma unroll
    for (int j = 0; j < 8; j++) acc[j] = 0.0f;
    for (int k = 0; k < 128; k++) {
        float a = cs[row * 128 + k];
#pragma unroll
        for (int j = 0; j < 8; j++) acc[j] += a * W_out[(c0 + j) * 128 + k];
    }
#pragma unroll
    for (int j = 0; j < 8; j++) {
        cvs[row * 128 + c0 + j] = acc[j];
        if (full) out[2048 + (g0 + row) * 128 + c0 + j] = acc[j];
    }
    __syncthreads();

    if (tid < 32) {
        int r = tid >> 1, c = tid & 1;
        float s = 0.0f;
        for (int k = 0; k < 128; k++) s += cvs[r * 128 + k] * W_cls[c * 128 + k];
        out[(g0 + r) * 2 + c] = s;
    }
    if (full && blockIdx.x == 0 && tid < 128) out[2048 + GRP * HDIM + tid] = ap[tid];
}

// ---------------- launch ----------------
extern "C" void kernel_launch(void* const* d_in, const int* in_sizes, int n_in,
                              void* d_out, int out_size) {
    const float* inputs = (const float*)d_in[0];
    const int* lens     = (const int*)d_in[1];
    const int* seg      = (const int*)d_in[2];
    const float* W_in   = (const float*)d_in[3];
    const float* gamma  = (const float*)d_in[4];
    const float* beta   = (const float*)d_in[5];
    const float* Wih    = (const float*)d_in[6];
    const float* Whh    = (const float*)d_in[7];
    const float* bih    = (const float*)d_in[8];
    const float* bhh    = (const float*)d_in[9];
    const float* ap     = (const float*)d_in[10];
    const float* W_out  = (const float*)d_in[11];
    const float* W_cls  = (const float*)d_in[12];
    float* out = (float*)d_out;

    const int fp_smem   = FP_SMEM_B32 * 4;   // 112128 B
    const int lstm_smem = 25344 * 4;         // 101376 B
    cudaFuncSetAttribute(k_fp, cudaFuncAttributeMaxDynamicSharedMemorySize, fp_smem);
    cudaFuncSetAttribute(k_lstm, cudaFuncAttributeMaxDynamicSharedMemorySize, lstm_smem);

    k_init<<<(GRP * HDIM + 255) / 256, 256>>>();
    k_hist<<<NPATH / 256, 256>>>(lens);
    k_scan<<<1, 32>>>();
    k_scatter<<<NPATH / 256, 256>>>(lens);
    k_rowlist<<<NPATH / 256, 256>>>(lens);
    k_prep<<<256, 256>>>(Whh, Wih, W_in);
    k_fp<<<RTOT / 128, 256, fp_smem>>>(inputs, gamma, beta, bih, bhh);
    k_lstm<<<NPATH / 32, 256, lstm_smem>>>(lens);
    k_logits<<<NPATH / 8, 256>>>(ap, seg);
    k_expsum<<<NPATH / 256, 256>>>(seg);
    k_wsum<<<NPATH / 8, 256>>>(seg);
    k_head<<<GRP / 16, 256>>>(W_out, W_cls, ap, out, out_size);
}

// round 11
// speedup vs baseline: 1.3564x; 1.0489x over previous
#include <cuda_runtime.h>
#include <cuda_bf16.h>
#include <cstdint>

#define NPATH 8192
#define LMAX 32
#define DIN 256
#define EDIM 128
#define HDIM 128
#define G4 512
#define GRP 1024
#define RTOT (NPATH*LMAX)
#define LN_EPS 1e-5f

typedef unsigned long long ull;

// ---------------- device scratch (static, no allocation) ----------------
__device__ float g_gi[(size_t)RTOT*G4]; // 512 MB
__device__ float g_WhhT[HDIM*G4];       // Whh^T [k][j]
__device__ __nv_bfloat16 g_WinH[EDIM*DIN];
__device__ __nv_bfloat16 g_WinL[EDIM*DIN];
__device__ __nv_bfloat16 g_WihH[G4*HDIM];
__device__ __nv_bfloat16 g_WihL[G4*HDIM];
__device__ float g_h[NPATH*HDIM];
__device__ float g_logits[NPATH];
__device__ float g_e[NPATH];
__device__ unsigned g_gmax[GRP];
__device__ float g_gsum[GRP];
__device__ float g_cnt[GRP];
__device__ float g_wsum[GRP*HDIM];
__device__ int g_lcnt[40];
__device__ int g_lstart[40];
__device__ int g_perm[NPATH];
__device__ int g_nrows;
__device__ int g_rows[RTOT];

__device__ __forceinline__ float sigm(float x) { return 1.0f / (1.0f + expf(-x)); }

__device__ __forceinline__ unsigned enc_f(float f) {
    unsigned u = __float_as_uint(f);
    return (u & 0x80000000u) ? ~u : (u | 0x80000000u);
}
__device__ __forceinline__ float dec_f(unsigned k) {
    return (k & 0x80000000u) ? __uint_as_float(k ^ 0x80000000u) : __uint_as_float(~k);
}

// ---------------- packed f32x2 helpers ----------------
__device__ __forceinline__ ull fma2(ull a, ull b, ull c) {
    ull d;
    asm("fma.rn.f32x2 %0, %1, %2, %3;" : "=l"(d) : "l"(a), "l"(b), "l"(c));
    return d;
}
__device__ __forceinline__ ull pack2(float x, float y) {
    ull d;
    asm("mov.b64 %0, {%1, %2};" : "=l"(d) : "f"(x), "f"(y));
    return d;
}
__device__ __forceinline__ float2 unpack2(ull v) {
    float2 r;
    asm("mov.b64 {%0, %1}, %2;" : "=f"(r.x), "=f"(r.y) : "l"(v));
    return r;
}

// ---------------- mma helper ----------------
#define MMA_BF16(Cr, a0, a1, a2, a3, b0, b1) \
    asm volatile("mma.sync.aligned.m16n8k16.row.col.f32.bf16.bf16.f32 " \
        "{%0,%1,%2,%3}, {%4,%5,%6,%7}, {%8,%9}, {%0,%1,%2,%3};" \
        : "+f"((Cr)[0]), "+f"((Cr)[1]), "+f"((Cr)[2]), "+f"((Cr)[3]) \
        : "r"(a0), "r"(a1), "r"(a2), "r"(a3), "r"(b0), "r"(b1))

// ---------------- sort kernels ----------------
__global__ void k_hist(const int* __restrict__ lens) {
    int n = blockIdx.x * 256 + threadIdx.x;
    if (n < NPATH) atomicAdd(&g_lcnt[lens[n]], 1);
}
__global__ void k_scan() {
    if (threadIdx.x == 0 && blockIdx.x == 0) {
        int run = 0;
        for (int l = LMAX; l >= 1; l--) { g_lstart[l] = run; run += g_lcnt[l]; }
    }
}
__global__ void k_scatter(const int* __restrict__ lens) {
    int n = blockIdx.x * 256 + threadIdx.x;
    if (n < NPATH) {
        int pos = atomicAdd(&g_lstart[lens[n]], 1);
        g_perm[pos] = n;
    }
}
__global__ void k_rowlist(const int* __restrict__ lens) {
    int n = blockIdx.x * 256 + threadIdx.x;
    if (n < NPATH) {
        int l = lens[n];
        int pos = atomicAdd(&g_nrows, l);
        int base = n * LMAX;
        for (int t = 0; t < l; t++) g_rows[pos + t] = base + t;
    }
}

// ---------------- kernel 0: transpose Whh + bf16-split W_in/Wih ----------------
__global__ void __launch_bounds__(256) k_prep(const float* __restrict__ Whh,
                                              const float* __restrict__ Wih,
                                              const float* __restrict__ W_in) {
    int idx = blockIdx.x * 256 + threadIdx.x;   // 65536 total
    {
        int j = idx >> 7, k = idx & 127;
        g_WhhT[k * G4 + j] = Whh[j * HDIM + k];
    }
    {
        float v = Wih[idx];
        __nv_bfloat16 h = __float2bfloat16(v);
        g_WihH[idx] = h;
        g_WihL[idx] = __float2bfloat16(v - __bfloat162float(h));
    }
    if (idx < EDIM * DIN) {
        float v = W_in[idx];
        __nv_bfloat16 h = __float2bfloat16(v);
        g_WinH[idx] = h;
        g_WinL[idx] = __float2bfloat16(v - __bfloat162float(h));
    }
}

// smem offsets (b32 units)
#define OFF_AH   0
#define OFF_AL   4608
#define OFF_XH   9216
#define OFF_XL   17920
#define OFF_RED  26624
#define OFF_GAM  27136
#define OFF_BET  27264
#define OFF_BIAS 27392
#define OFF_SROW 27904
#define FP_SMEM_B32 28032

// ---------------- kernel 1: mma-based fused projection+LN+tanh + gate GEMM ----------------
__global__ void __launch_bounds__(256, 2) k_fp(const float* __restrict__ inp,
                                               const float* __restrict__ gamma,
                                               const float* __restrict__ beta,
                                               const float* __restrict__ bih,
                                               const float* __restrict__ bhh) {
    extern __shared__ uint32_t s32[];
    __nv_bfloat16* Ah16 = (__nv_bfloat16*)(s32 + OFF_AH);
    __nv_bfloat16* Al16 = (__nv_bfloat16*)(s32 + OFF_AL);
    const uint32_t* Ah32 = s32 + OFF_AH;
    const uint32_t* Al32 = s32 + OFF_AL;
    __nv_bfloat162* Xh2 = (__nv_bfloat162*)(s32 + OFF_XH);
    __nv_bfloat162* Xl2 = (__nv_bfloat162*)(s32 + OFF_XL);
    const uint32_t* Xh32 = s32 + OFF_XH;
    const uint32_t* Xl32 = s32 + OFF_XL;
    float2* red = (float2*)(s32 + OFF_RED);
    float* sgam = (float*)(s32 + OFF_GAM);
    float* sbet = (float*)(s32 + OFF_BET);
    float* sbias = (float*)(s32 + OFF_BIAS);
    int* srow = (int*)(s32 + OFF_SROW);

    const int tid = threadIdx.x;
    const int lane = tid & 31, wid = tid >> 5;
    const int warp_m = wid & 3, warp_n = wid >> 2;
    const int r = lane >> 2, cq = lane & 3;
    const int base = blockIdx.x * 128;
    const int nrows = g_nrows;
    if (base >= nrows) return;

    if (tid < 128) {
        srow[tid] = (base + tid < nrows) ? g_rows[base + tid] : g_rows[base];
        sgam[tid] = gamma[tid];
        sbet[tid] = beta[tid];
    }
    sbias[tid] = bih[tid] + bhh[tid];
    sbias[tid + 256] = bih[tid + 256] + bhh[tid + 256];
    __syncthreads();

    // phase 1: C = inp @ W_in^T
    float C[2][8][4];
#pragma unroll
    for (int mt = 0; mt < 2; mt++)
#pragma unroll
        for (int nt = 0; nt < 8; nt++)
#pragma unroll
            for (int v = 0; v < 4; v++) C[mt][nt][v] = 0.0f;

    for (int ks = 0; ks < 4; ks++) {
        __syncthreads();
#pragma unroll
        for (int s = 0; s < 32; s++) {
            int idx = tid + s * 256;
            int row = idx >> 6, c = idx & 63;
            float v = inp[(size_t)srow[row] * DIN + ks * 64 + c];
            __nv_bfloat16 h = __float2bfloat16(v);
            Ah16[row * 72 + c] = h;
            Al16[row * 72 + c] = __float2bfloat16(v - __bfloat162float(h));
        }
        __syncthreads();
#pragma unroll
        for (int k4 = 0; k4 < 4; k4++) {
            const int k8 = k4 * 8;
            uint32_t ah[2][4], al[2][4];
#pragma unroll
            for (int mt = 0; mt < 2; mt++) {
                int row = warp_m * 32 + mt * 16 + r;
                ah[mt][0] = Ah32[row * 36 + k8 + cq];
                ah[mt][1] = Ah32[(row + 8) * 36 + k8 + cq];
                ah[mt][2] = Ah32[row * 36 + k8 + cq + 4];
                ah[mt][3] = Ah32[(row + 8) * 36 + k8 + cq + 4];
                al[mt][0] = Al32[row * 36 + k8 + cq];
                al[mt][1] = Al32[(row + 8) * 36 + k8 + cq];
                al[mt][2] = Al32[row * 36 + k8 + cq + 4];
                al[mt][3] = Al32[(row + 8) * 36 + k8 + cq + 4];
            }
            const int kbg = ks * 64 + k4 * 16;
#pragma unroll
            for (int nt = 0; nt < 8; nt++) {
                int n = warp_n * 64 + nt * 8 + r;
                const uint32_t* Bh = (const uint32_t*)(g_WinH + n * DIN + kbg + 2 * cq);
                const uint32_t* Bl = (const uint32_t*)(g_WinL + n * DIN + kbg + 2 * cq);
                uint32_t bh0 = Bh[0], bh1 = Bh[4];
                uint32_t bl0 = Bl[0], bl1 = Bl[4];
#pragma unroll
                for (int mt = 0; mt < 2; mt++) {
                    MMA_BF16(C[mt][nt], ah[mt][0], ah[mt][1], ah[mt][2], ah[mt][3], bh0, bh1);
                    MMA_BF16(C[mt][nt], ah[mt][0], ah[mt][1], ah[mt][2], ah[mt][3], bl0, bl1);
                    MMA_BF16(C[mt][nt], al[mt][0], al[mt][1], al[mt][2], al[mt][3], bh0, bh1);
                }
            }
        }
    }

    // LN + tanh epilogue -> Xh/Xl
    __syncthreads();
#pragma unroll
    for (int mt = 0; mt < 2; mt++) {
        float sA = 0.f, qA = 0.f, sB = 0.f, qB = 0.f;
#pragma unroll
        for (int nt = 0; nt < 8; nt++) {
            sA += C[mt][nt][0] + C[mt][nt][1];
            qA += C[mt][nt][0] * C[mt][nt][0] + C[mt][nt][1] * C[mt][nt][1];
            sB += C[mt][nt][2] + C[mt][nt][3];
            qB += C[mt][nt][2] * C[mt][nt][2] + C[mt][nt][3] * C[mt][nt][3];
        }
#pragma unroll
        for (int m = 1; m <= 2; m <<= 1) {
            sA += __shfl_xor_sync(0xffffffffu, sA, m);
            qA += __shfl_xor_sync(0xffffffffu, qA, m);
            sB += __shfl_xor_sync(0xffffffffu, sB, m);
            qB += __shfl_xor_sync(0xffffffffu, qB, m);
        }
        if (cq == 0) {
            int rowA = warp_m * 32 + mt * 16 + r;
            red[rowA * 2 + warp_n] = make_float2(sA, qA);
            red[(rowA + 8) * 2 + warp_n] = make_float2(sB, qB);
        }
    }
    __syncthreads();

    float muv[2][2], rsv[2][2];
#pragma unroll
    for (int mt = 0; mt < 2; mt++)
#pragma unroll
        for (int hb = 0; hb < 2; hb++) {
            int row = warp_m * 32 + mt * 16 + r + hb * 8;
            float2 p0 = red[row * 2 + 0], p1 = red[row * 2 + 1];
            float s = p0.x + p1.x, q = p0.y + p1.y;
            float mu = s * (1.0f / 128.0f);
            float var = q * (1.0f / 128.0f) - mu * mu;
            muv[mt][hb] = mu;
            rsv[mt][hb] = rsqrtf(var + LN_EPS);
        }

#pragma unroll
    for (int mt = 0; mt < 2; mt++) {
#pragma unroll
        for (int nt = 0; nt < 8; nt++) {
            int col = warp_n * 64 + nt * 8 + 2 * cq;
            int c2 = warp_n * 32 + nt * 4 + cq;
            float g0 = sgam[col], g1 = sgam[col + 1];
            float b0 = sbet[col], b1 = sbet[col + 1];
            int rowA = warp_m * 32 + mt * 16 + r;
            {
                float x0 = tanhf((C[mt][nt][0] - muv[mt][0]) * rsv[mt][0] * g0 + b0);
                float x1 = tanhf((C[mt][nt][1] - muv[mt][0]) * rsv[mt][0] * g1 + b1);
                __nv_bfloat16 h0 = __float2bfloat16(x0);
                __nv_bfloat16 h1 = __float2bfloat16(x1);
                __nv_bfloat162 hv; hv.x = h0; hv.y = h1;
                __nv_bfloat162 lv;
                lv.x = __float2bfloat16(x0 - __bfloat162float(h0));
                lv.y = __float2bfloat16(x1 - __bfloat162float(h1));
                Xh2[rowA * 68 + c2] = hv;
                Xl2[rowA * 68 + c2] = lv;
            }
            {
                float x0 = tanhf((C[mt][nt][2] - muv[mt][1]) * rsv[mt][1] * g0 + b0);
                float x1 = tanhf((C[mt][nt][3] - muv[mt][1]) * rsv[mt][1] * g1 + b1);
                __nv_bfloat16 h0 = __float2bfloat16(x0);
                __nv_bfloat16 h1 = __float2bfloat16(x1);
                __nv_bfloat162 hv; hv.x = h0; hv.y = h1;
                __nv_bfloat162 lv;
                lv.x = __float2bfloat16(x0 - __bfloat162float(h0));
                lv.y = __float2bfloat16(x1 - __bfloat162float(h1));
                Xh2[(rowA + 8) * 68 + c2] = hv;
                Xl2[(rowA + 8) * 68 + c2] = lv;
            }
        }
    }
    __syncthreads();

    // phase 2: gi = X @ Wih^T + b
    for (int pass = 0; pass < 8; pass++) {
        float D[2][4][4];
#pragma unroll
        for (int mt = 0; mt < 2; mt++)
#pragma unroll
            for (int nt = 0; nt < 4; nt++)
#pragma unroll
                for (int v = 0; v < 4; v++) D[mt][nt][v] = 0.0f;

#pragma unroll
        for (int k = 0; k < 8; k++) {
            const int k8 = k * 8;
            uint32_t ah[2][4], al[2][4];
#pragma unroll
            for (int mt = 0; mt < 2; mt++) {
                int row = warp_m * 32 + mt * 16 + r;
                ah[mt][0] = Xh32[row * 68 + k8 + cq];
                ah[mt][1] = Xh32[(row + 8) * 68 + k8 + cq];
                ah[mt][2] = Xh32[row * 68 + k8 + cq + 4];
                ah[mt][3] = Xh32[(row + 8) * 68 + k8 + cq + 4];
                al[mt][0] = Xl32[row * 68 + k8 + cq];
                al[mt][1] = Xl32[(row + 8) * 68 + k8 + cq];
                al[mt][2] = Xl32[row * 68 + k8 + cq + 4];
                al[mt][3] = Xl32[(row + 8) * 68 + k8 + cq + 4];
            }
#pragma unroll
            for (int nt = 0; nt < 4; nt++) {
                int n = pass * 64 + warp_n * 32 + nt * 8 + r;
                const uint32_t* Bh = (const uint32_t*)(g_WihH + n * HDIM + k * 16 + 2 * cq);
                const uint32_t* Bl = (const uint32_t*)(g_WihL + n * HDIM + k * 16 + 2 * cq);
                uint32_t bh0 = Bh[0], bh1 = Bh[4];
                uint32_t bl0 = Bl[0], bl1 = Bl[4];
#pragma unroll
                for (int mt = 0; mt < 2; mt++) {
                    MMA_BF16(D[mt][nt], ah[mt][0], ah[mt][1], ah[mt][2], ah[mt][3], bh0, bh1);
                    MMA_BF16(D[mt][nt], ah[mt][0], ah[mt][1], ah[mt][2], ah[mt][3], bl0, bl1);
                    MMA_BF16(D[mt][nt], al[mt][0], al[mt][1], al[mt][2], al[mt][3], bh0, bh1);
                }
            }
        }
#pragma unroll
        for (int mt = 0; mt < 2; mt++) {
#pragma unroll
            for (int nt = 0; nt < 4; nt++) {
                int col = pass * 64 + warp_n * 32 + nt * 8 + 2 * cq;
                float2 bb = *(const float2*)&sbias[col];
                int rowA = warp_m * 32 + mt * 16 + r;
                if (base + rowA < nrows) {
                    float2 o = make_float2(D[mt][nt][0] + bb.x, D[mt][nt][1] + bb.y);
                    *(float2*)&g_gi[(size_t)srow[rowA] * G4 + col] = o;
                }
                int rowB = rowA + 8;
                if (base + rowB < nrows) {
                    float2 o = make_float2(D[mt][nt][2] + bb.x, D[mt][nt][3] + bb.y);
                    *(float2*)&g_gi[(size_t)srow[rowB] * G4 + col] = o;
                }
            }
        }
    }
}

// ---------------- kernel 2: LSTM recurrence v2 ----------------
// 32 sorted paths/block, 256 thr. Warp = (pg 0..1 paths, cg 0..3 col-slice).
// Lane owns col c = cg*32+lane across all 4 gates; 16 paths packed in f32x2.
// A: broadcast LDS.128 from hs[k][path] (transposed). B: LDG from L2 WhhT.
// No B staging, no gate smem round-trip; 2 syncs/timestep.
__global__ void __launch_bounds__(256, 2) k_lstm(const int* __restrict__ lens) {
    __shared__ float hs[128 * 36];    // [k][paths], stride 36 for alignment
    __shared__ int ln_s[32];
    __shared__ int sp_s[32];
    __shared__ int maxlen_s;

    const int tid = threadIdx.x;
    const int lane = tid & 31, wid = tid >> 5;
    const int pg = wid >> 2;          // path group: 16 paths
    const int cg = wid & 3;           // col slice
    const int c = cg * 32 + lane;     // j index 0..127
    const int p0 = pg * 16;
    const int bid = blockIdx.x;
    const int gidx = (bid < 148) ? bid : (403 - bid);
    const int n0 = gidx * 32;

#pragma unroll
    for (int s = 0; s < 18; s++) {
        int idx = tid + s * 256;
        if (idx < 128 * 36) hs[idx] = 0.0f;
    }
    if (tid < 32) {
        int pid = g_perm[n0 + tid];
        sp_s[tid] = pid;
        int l = lens[pid];
        ln_s[tid] = l;
#pragma unroll
        for (int m = 16; m >= 1; m >>= 1) l = max(l, __shfl_xor_sync(0xffffffffu, l, m));
        if (tid == 0) maxlen_s = l;
    }
    __syncthreads();

    int wmax = 0;
#pragma unroll
    for (int i = 0; i < 16; i++) wmax = max(wmax, ln_s[p0 + i]);
    const int blkmax = maxlen_s;

    float c_reg[16];
#pragma unroll
    for (int i = 0; i < 16; i++) c_reg[i] = 0.0f;

    for (int t = 0; t < blkmax; t++) {
        ull acc[8][4];
#pragma unroll
        for (int pp = 0; pp < 8; pp++)
#pragma unroll
            for (int g = 0; g < 4; g++) acc[pp][g] = 0ull;

        const bool active = (t < wmax);
        if (active) {
#pragma unroll 8
            for (int kk = 0; kk < 128; kk++) {
                const float* hrow = &hs[kk * 36 + p0];
                ulonglong2 a01 = *(const ulonglong2*)(hrow);
                ulonglong2 a23 = *(const ulonglong2*)(hrow + 4);
                ulonglong2 a45 = *(const ulonglong2*)(hrow + 8);
                ulonglong2 a67 = *(const ulonglong2*)(hrow + 12);
                ull A[8] = {a01.x, a01.y, a23.x, a23.y, a45.x, a45.y, a67.x, a67.y};
                const float* wrow = &g_WhhT[kk * G4 + c];
                float b0 = wrow[0];
                float b1 = wrow[128];
                float b2 = wrow[256];
                float b3 = wrow[384];
                ull B[4] = {pack2(b0, b0), pack2(b1, b1), pack2(b2, b2), pack2(b3, b3)};
#pragma unroll
                for (int pp = 0; pp < 8; pp++) {
                    acc[pp][0] = fma2(A[pp], B[0], acc[pp][0]);
                    acc[pp][1] = fma2(A[pp], B[1], acc[pp][1]);
                    acc[pp][2] = fma2(A[pp], B[2], acc[pp][2]);
                    acc[pp][3] = fma2(A[pp], B[3], acc[pp][3]);
                }
            }
        }
        __syncthreads();   // all hs reads done before updates

        if (active) {
#pragma unroll
            for (int pp = 0; pp < 8; pp++) {
                int pa = p0 + 2 * pp, pb = pa + 1;
                bool la = (t < ln_s[pa]);
                bool lb = (t < ln_s[pb]);
                if (la | lb) {
                    float2 vi = unpack2(acc[pp][0]);
                    float2 vf = unpack2(acc[pp][1]);
                    float2 vg = unpack2(acc[pp][2]);
                    float2 vo = unpack2(acc[pp][3]);
                    float ha = 0.0f, hb = 0.0f;
                    if (la) {
                        size_t row = ((size_t)sp_s[pa] * LMAX + t) * G4 + c;
                        float xi = g_gi[row] + vi.x;
                        float xf = g_gi[row + 128] + vf.x;
                        float xg = g_gi[row + 256] + vg.x;
                        float xo = g_gi[row + 384] + vo.x;
                        float cn = sigm(xf) * c_reg[2 * pp] + sigm(xi) * tanhf(xg);
                        c_reg[2 * pp] = cn;
                        ha = sigm(xo) * tanhf(cn);
                    }
                    if (lb) {
                        size_t row = ((size_t)sp_s[pb] * LMAX + t) * G4 + c;
                        float xi = g_gi[row] + vi.y;
                        float xf = g_gi[row + 128] + vf.y;
                        float xg = g_gi[row + 256] + vg.y;
                        float xo = g_gi[row + 384] + vo.y;
                        float cn = sigm(xf) * c_reg[2 * pp + 1] + sigm(xi) * tanhf(xg);
                        c_reg[2 * pp + 1] = cn;
                        hb = sigm(xo) * tanhf(cn);
                    }
                    if (la && lb) {
                        *(float2*)&hs[c * 36 + pa] = make_float2(ha, hb);
                    } else if (la) {
                        hs[c * 36 + pa] = ha;
                    } else {
                        hs[c * 36 + pb] = hb;
                    }
                }
            }
        }
        __syncthreads();
    }

    // final h store: g_h[pid][k] = hs[k][n]
#pragma unroll
    for (int s = 0; s < 16; s++) {
        int idx = tid + s * 256;
        int n = idx & 31, k = idx >> 5;
        g_h[(size_t)sp_s[n] * HDIM + k] = hs[k * 36 + n];
    }
}

// ---------------- kernel 3a: init accumulators (+ counters) ----------------
__global__ void k_init() {
    int i = blockIdx.x * blockDim.x + threadIdx.x;
    if (i < GRP * HDIM) g_wsum[i] = 0.0f;
    if (i < GRP) {
        g_gsum[i] = 0.0f;
        g_cnt[i] = 0.0f;
        g_gmax[i] = 0u;
    }
    if (i < 40) g_lcnt[i] = 0;
    if (i == 0) g_nrows = 0;
}

// ---------------- kernel 3b: attention logits + segment max ----------------
__global__ void __launch_bounds__(256) k_logits(const float* __restrict__ ap,
                                                const int* __restrict__ seg) {
    int w = threadIdx.x >> 5, lane = threadIdx.x & 31;
    int n = blockIdx.x * 8 + w;
    float s = 0.0f;
#pragma unroll
    for (int q = 0; q < 4; q++) s += g_h[n * HDIM + lane + 32 * q] * ap[lane + 32 * q];
#pragma unroll
    for (int m = 16; m >= 1; m >>= 1) s += __shfl_xor_sync(0xffffffffu, s, m);
    if (lane == 0) {
        g_logits[n] = s;
        atomicMax(&g_gmax[seg[n]], enc_f(s));
    }
}

// ---------------- kernel 3c: exp + segment sum + count ----------------
__global__ void __launch_bounds__(256) k_expsum(const int* __restrict__ seg) {
    int n = blockIdx.x * 256 + threadIdx.x;
    int g = seg[n];
    float e = expf(g_logits[n] - dec_f(g_gmax[g]));
    g_e[n] = e;
    atomicAdd(&g_gsum[g], e);
    atomicAdd(&g_cnt[g], 1.0f);
}

// ---------------- kernel 3d: weighted hidden sum per group ----------------
__global__ void __launch_bounds__(256) k_wsum(const int* __restrict__ seg) {
    int w = threadIdx.x >> 5, lane = threadIdx.x & 31;
    int n = blockIdx.x * 8 + w;
    float e = g_e[n];
    int g = seg[n];
#pragma unroll
    for (int q = 0; q < 4; q++)
        atomicAdd(&g_wsum[g * HDIM + lane + 32 * q], e * g_h[n * HDIM + lane + 32 * q]);
}

// ---------------- kernel 4: head ----------------
__global__ void __launch_bounds__(256) k_head(const float* __restrict__ W_out,
                                              const float* __restrict__ W_cls,
                                              const float* __restrict__ ap,
                                              float* __restrict__ out,
                                              int out_size) {
    __shared__ float cs[16 * 128];
    __shared__ float cvs[16 * 128];
    const int tid = threadIdx.x;
    const int g0 = blockIdx.x * 16;
    const bool full = (out_size >= 2048 + GRP * HDIM + HDIM);

#pragma unroll
    for (int s = 0; s < 8; s++) {
        int idx = tid + s * 256;
        int gg = idx >> 7, k = idx & 127;
        int gi = g0 + gg;
        cs[gg * 128 + k] = g_wsum[gi * HDIM + k] / (g_gsum[gi] * g_cnt[gi]);
    }
    __syncthreads();

    int row = tid >> 4;
    int c0 = (tid & 15) * 8;
    float acc[8];
#pragma unroll
    for (int j = 0; j < 8; j++) acc[j] = 0.0f;
    for (int k = 0; k < 128; k++) {
        float a = cs[row * 128 + k];
#pragma unroll
        for (int j = 0; j < 8; j++) acc[j] += a * W_out[(c0 + j) * 128 + k];
    }
#pragma unroll
    for (int j = 0; j < 8; j++) {
        cvs[row * 128 + c0 + j] = acc[j];
        if (full) out[2048 + (g0 + row) * 128 + c0 + j] = acc[j];
    }
    __syncthreads();

    if (tid < 32) {
        int r = tid >> 1, cc = tid & 1;
        float s = 0.0f;
        for (int k = 0; k < 128; k++) s += cvs[r * 128 + k] * W_cls[cc * 128 + k];
        out[(g0 + r) * 2 + cc] = s;
    }
    if (full && blockIdx.x == 0 && tid < 128) out[2048 + GRP * HDIM + tid] = ap[tid];
}

// ---------------- launch ----------------
extern "C" void kernel_launch(void* const* d_in, const int* in_sizes, int n_in,
                              void* d_out, int out_size) {
    const float* inputs = (const float*)d_in[0];
    const int* lens     = (const int*)d_in[1];
    const int* seg      = (const int*)d_in[2];
    const float* W_in   = (const float*)d_in[3];
    const float* gamma  = (const float*)d_in[4];
    const float* beta   = (const float*)d_in[5];
    const float* Wih    = (const float*)d_in[6];
    const float* Whh    = (const float*)d_in[7];
    const float* bih    = (const float*)d_in[8];
    const float* bhh    = (const float*)d_in[9];
    const float* ap     = (const float*)d_in[10];
    const float* W_out  = (const float*)d_in[11];
    const float* W_cls  = (const float*)d_in[12];
    float* out = (float*)d_out;

    const int fp_smem = FP_SMEM_B32 * 4;   // 112128 B
    cudaFuncSetAttribute(k_fp, cudaFuncAttributeMaxDynamicSharedMemorySize, fp_smem);

    // k_fp in the 4th launch slot (the one ncu captures)
    k_init<<<(GRP * HDIM + 255) / 256, 256>>>();
    k_rowlist<<<NPATH / 256, 256>>>(lens);
    k_prep<<<256, 256>>>(Whh, Wih, W_in);
    k_fp<<<RTOT / 128, 256, fp_smem>>>(inputs, gamma, beta, bih, bhh);
    k_hist<<<NPATH / 256, 256>>>(lens);
    k_scan<<<1, 32>>>();
    k_scatter<<<NPATH / 256, 256>>>(lens);
    k_lstm<<<NPATH / 32, 256>>>(lens);
    k_logits<<<NPATH / 8, 256>>>(ap, seg);
    k_expsum<<<NPATH / 256, 256>>>(seg);
    k_wsum<<<NPATH / 8, 256>>>(seg);
    k_head<<<GRP / 16, 256>>>(W_out, W_cls, ap, out, out_size);
}

// round 12
// speedup vs baseline: 1.5663x; 1.1548x over previous
#include <cuda_runtime.h>
#include <cuda_bf16.h>
#include <cstdint>

#define NPATH 8192
#define LMAX 32
#define DIN 256
#define EDIM 128
#define HDIM 128
#define G4 512
#define GRP 1024
#define RTOT (NPATH*LMAX)
#define LN_EPS 1e-5f

typedef unsigned long long ull;

// ---------------- device scratch (static, no allocation) ----------------
__device__ float g_gi[(size_t)RTOT*G4]; // 512 MB
__device__ float g_WhhT[HDIM*G4];       // Whh^T [k][j]
__device__ __nv_bfloat16 g_WinH[EDIM*DIN];
__device__ __nv_bfloat16 g_WinL[EDIM*DIN];
__device__ __nv_bfloat16 g_WihH[G4*HDIM];
__device__ __nv_bfloat16 g_WihL[G4*HDIM];
__device__ uint4 g_WinP[EDIM*16*4];     // fragment-packed: [(n*16+kf)*4+cq] = {bh0,bh1,bl0,bl1}
__device__ uint4 g_WihP[G4*8*4];        // [(n*8+kf)*4+cq]
__device__ float g_h[NPATH*HDIM];
__device__ float g_logits[NPATH];
__device__ float g_e[NPATH];
__device__ unsigned g_gmax[GRP];
__device__ float g_gsum[GRP];
__device__ float g_cnt[GRP];
__device__ float g_wsum[GRP*HDIM];
__device__ int g_lcnt[40];
__device__ int g_lstart[40];
__device__ int g_perm[NPATH];
__device__ int g_nrows;
__device__ int g_rows[RTOT];

__device__ __forceinline__ float sigm(float x) { return 1.0f / (1.0f + expf(-x)); }

__device__ __forceinline__ unsigned enc_f(float f) {
    unsigned u = __float_as_uint(f);
    return (u & 0x80000000u) ? ~u : (u | 0x80000000u);
}
__device__ __forceinline__ float dec_f(unsigned k) {
    return (k & 0x80000000u) ? __uint_as_float(k ^ 0x80000000u) : __uint_as_float(~k);
}

// ---------------- packed f32x2 helpers ----------------
__device__ __forceinline__ ull fma2(ull a, ull b, ull c) {
    ull d;
    asm("fma.rn.f32x2 %0, %1, %2, %3;" : "=l"(d) : "l"(a), "l"(b), "l"(c));
    return d;
}
__device__ __forceinline__ ull pack2(float x, float y) {
    ull d;
    asm("mov.b64 %0, {%1, %2};" : "=l"(d) : "f"(x), "f"(y));
    return d;
}
__device__ __forceinline__ float2 unpack2(ull v) {
    float2 r;
    asm("mov.b64 {%0, %1}, %2;" : "=f"(r.x), "=f"(r.y) : "l"(v));
    return r;
}

// ---------------- mma / ldmatrix helpers ----------------
#define MMA_BF16(Cr, a0, a1, a2, a3, b0, b1) \
    asm volatile("mma.sync.aligned.m16n8k16.row.col.f32.bf16.bf16.f32 " \
        "{%0,%1,%2,%3}, {%4,%5,%6,%7}, {%8,%9}, {%0,%1,%2,%3};" \
        : "+f"((Cr)[0]), "+f"((Cr)[1]), "+f"((Cr)[2]), "+f"((Cr)[3]) \
        : "r"(a0), "r"(a1), "r"(a2), "r"(a3), "r"(b0), "r"(b1))

#define LDSM_X4(r0, r1, r2, r3, a) \
    asm volatile("ldmatrix.sync.aligned.m8n8.x4.shared.b16 {%0,%1,%2,%3}, [%4];" \
        : "=r"(r0), "=r"(r1), "=r"(r2), "=r"(r3) : "r"(a))

__device__ __forceinline__ uint32_t smem_u32(const void* p) {
    uint32_t a;
    asm("{ .reg .u64 t; cvta.to.shared.u64 t, %1; cvt.u32.u64 %0, t; }" : "=r"(a) : "l"(p));
    return a;
}

// ---------------- sort kernels ----------------
__global__ void k_hist(const int* __restrict__ lens) {
    int n = blockIdx.x * 256 + threadIdx.x;
    if (n < NPATH) atomicAdd(&g_lcnt[lens[n]], 1);
}
__global__ void k_scan() {
    if (threadIdx.x == 0 && blockIdx.x == 0) {
        int run = 0;
        for (int l = LMAX; l >= 1; l--) { g_lstart[l] = run; run += g_lcnt[l]; }
    }
}
__global__ void k_scatter(const int* __restrict__ lens) {
    int n = blockIdx.x * 256 + threadIdx.x;
    if (n < NPATH) {
        int pos = atomicAdd(&g_lstart[lens[n]], 1);
        g_perm[pos] = n;
    }
}
__global__ void k_rowlist(const int* __restrict__ lens) {
    int n = blockIdx.x * 256 + threadIdx.x;
    if (n < NPATH) {
        int l = lens[n];
        int pos = atomicAdd(&g_nrows, l);
        int base = n * LMAX;
        for (int t = 0; t < l; t++) g_rows[pos + t] = base + t;
    }
}

// ---------------- kernel 0a: transpose Whh + bf16-split W_in/Wih ----------------
__global__ void __launch_bounds__(256) k_prep(const float* __restrict__ Whh,
                                              const float* __restrict__ Wih,
                                              const float* __restrict__ W_in) {
    int idx = blockIdx.x * 256 + threadIdx.x;   // 65536 total
    {
        int j = idx >> 7, k = idx & 127;
        g_WhhT[k * G4 + j] = Whh[j * HDIM + k];
    }
    {
        float v = Wih[idx];
        __nv_bfloat16 h = __float2bfloat16(v);
        g_WihH[idx] = h;
        g_WihL[idx] = __float2bfloat16(v - __bfloat162float(h));
    }
    if (idx < EDIM * DIN) {
        float v = W_in[idx];
        __nv_bfloat16 h = __float2bfloat16(v);
        g_WinH[idx] = h;
        g_WinL[idx] = __float2bfloat16(v - __bfloat162float(h));
    }
}

// ---------------- kernel 0b: pack B fragments as uint4 {bh0,bh1,bl0,bl1} ----------------
__global__ void __launch_bounds__(256) k_prep2() {
    int idx = blockIdx.x * 256 + threadIdx.x;   // 24576 total
    if (idx < EDIM * 16 * 4) {
        int cq = idx & 3, kf = (idx >> 2) & 15, n = idx >> 6;
        int e = n * DIN + kf * 16 + 2 * cq;
        uint4 v;
        v.x = *(const uint32_t*)&g_WinH[e];
        v.y = *(const uint32_t*)&g_WinH[e + 8];
        v.z = *(const uint32_t*)&g_WinL[e];
        v.w = *(const uint32_t*)&g_WinL[e + 8];
        g_WinP[idx] = v;
    } else if (idx < EDIM * 16 * 4 + G4 * 8 * 4) {
        int i2 = idx - EDIM * 16 * 4;
        int cq = i2 & 3, kf = (i2 >> 2) & 7, n = i2 >> 5;
        int e = n * HDIM + kf * 16 + 2 * cq;
        uint4 v;
        v.x = *(const uint32_t*)&g_WihH[e];
        v.y = *(const uint32_t*)&g_WihH[e + 8];
        v.z = *(const uint32_t*)&g_WihL[e];
        v.w = *(const uint32_t*)&g_WihL[e + 8];
        g_WihP[i2] = v;
    }
}

// smem offsets (b32 units)
#define OFF_AH   0
#define OFF_AL   4608
#define OFF_XH   9216
#define OFF_XL   17920
#define OFF_RED  26624
#define OFF_GAM  27136
#define OFF_BET  27264
#define OFF_BIAS 27392
#define OFF_SROW 27904
#define FP_SMEM_B32 28032

// ---------------- kernel 1: mma-based fused projection+LN+tanh + gate GEMM ----------------
__global__ void __launch_bounds__(256, 2) k_fp(const float* __restrict__ inp,
                                               const float* __restrict__ gamma,
                                               const float* __restrict__ beta,
                                               const float* __restrict__ bih,
                                               const float* __restrict__ bhh) {
    extern __shared__ uint32_t s32[];
    __nv_bfloat16* Ah16 = (__nv_bfloat16*)(s32 + OFF_AH);   // [128][72] bf16
    __nv_bfloat16* Al16 = (__nv_bfloat16*)(s32 + OFF_AL);
    __nv_bfloat162* Xh2 = (__nv_bfloat162*)(s32 + OFF_XH);  // [128][68] b32 stride
    __nv_bfloat162* Xl2 = (__nv_bfloat162*)(s32 + OFF_XL);
    float2* red = (float2*)(s32 + OFF_RED);
    float* sgam = (float*)(s32 + OFF_GAM);
    float* sbet = (float*)(s32 + OFF_BET);
    float* sbias = (float*)(s32 + OFF_BIAS);
    int* srow = (int*)(s32 + OFF_SROW);

    const int tid = threadIdx.x;
    const int lane = tid & 31, wid = tid >> 5;
    const int warp_m = wid & 3, warp_n = wid >> 2;
    const int r = lane >> 2, cq = lane & 3;
    const int base = blockIdx.x * 128;
    const int nrows = g_nrows;
    if (base >= nrows) return;

    // ldmatrix lane geometry
    const int Lrow = ((lane >> 3) & 1) * 8 + (lane & 7);
    const int Lk8 = (lane >> 4) * 8;   // bf16 col offset within 16-col fragment

    if (tid < 128) {
        srow[tid] = (base + tid < nrows) ? g_rows[base + tid] : g_rows[base];
        sgam[tid] = gamma[tid];
        sbet[tid] = beta[tid];
    }
    sbias[tid] = bih[tid] + bhh[tid];
    sbias[tid + 256] = bih[tid + 256] + bhh[tid + 256];
    __syncthreads();

    // per-lane LDSM base addresses (bytes)
    uint32_t aAh[2], aAl[2], aXh[2], aXl[2];
#pragma unroll
    for (int mt = 0; mt < 2; mt++) {
        int row = warp_m * 32 + mt * 16 + Lrow;
        aAh[mt] = smem_u32(Ah16) + (row * 72 + Lk8) * 2;
        aAl[mt] = smem_u32(Al16) + (row * 72 + Lk8) * 2;
        aXh[mt] = smem_u32(Xh2) + row * 68 * 4 + Lk8 * 2;
        aXl[mt] = smem_u32(Xl2) + row * 68 * 4 + Lk8 * 2;
    }

    // ================= phase 1: C = inp @ W_in^T =================
    float C[2][8][4];
#pragma unroll
    for (int mt = 0; mt < 2; mt++)
#pragma unroll
        for (int nt = 0; nt < 8; nt++)
#pragma unroll
            for (int v = 0; v < 4; v++) C[mt][nt][v] = 0.0f;

    for (int ks = 0; ks < 4; ks++) {
        __syncthreads();
#pragma unroll
        for (int s = 0; s < 32; s++) {
            int idx = tid + s * 256;
            int row = idx >> 6, c = idx & 63;
            float v = inp[(size_t)srow[row] * DIN + ks * 64 + c];
            __nv_bfloat16 h = __float2bfloat16(v);
            Ah16[row * 72 + c] = h;
            Al16[row * 72 + c] = __float2bfloat16(v - __bfloat162float(h));
        }
        __syncthreads();
#pragma unroll
        for (int k4 = 0; k4 < 4; k4++) {
            uint32_t ah[2][4], al[2][4];
#pragma unroll
            for (int mt = 0; mt < 2; mt++) {
                LDSM_X4(ah[mt][0], ah[mt][1], ah[mt][2], ah[mt][3], aAh[mt] + k4 * 32);
                LDSM_X4(al[mt][0], al[mt][1], al[mt][2], al[mt][3], aAl[mt] + k4 * 32);
            }
            const int kf = ks * 4 + k4;
#pragma unroll
            for (int nt = 0; nt < 8; nt++) {
                int n = warp_n * 64 + nt * 8 + r;
                uint4 bv = g_WinP[(n * 16 + kf) * 4 + cq];
#pragma unroll
                for (int mt = 0; mt < 2; mt++) {
                    MMA_BF16(C[mt][nt], ah[mt][0], ah[mt][1], ah[mt][2], ah[mt][3], bv.x, bv.y);
                    MMA_BF16(C[mt][nt], ah[mt][0], ah[mt][1], ah[mt][2], ah[mt][3], bv.z, bv.w);
                    MMA_BF16(C[mt][nt], al[mt][0], al[mt][1], al[mt][2], al[mt][3], bv.x, bv.y);
                }
            }
        }
    }

    // ================= LN + tanh epilogue -> Xh/Xl =================
    __syncthreads();
#pragma unroll
    for (int mt = 0; mt < 2; mt++) {
        float sA = 0.f, qA = 0.f, sB = 0.f, qB = 0.f;
#pragma unroll
        for (int nt = 0; nt < 8; nt++) {
            sA += C[mt][nt][0] + C[mt][nt][1];
            qA += C[mt][nt][0] * C[mt][nt][0] + C[mt][nt][1] * C[mt][nt][1];
            sB += C[mt][nt][2] + C[mt][nt][3];
            qB += C[mt][nt][2] * C[mt][nt][2] + C[mt][nt][3] * C[mt][nt][3];
        }
#pragma unroll
        for (int m = 1; m <= 2; m <<= 1) {
            sA += __shfl_xor_sync(0xffffffffu, sA, m);
            qA += __shfl_xor_sync(0xffffffffu, qA, m);
            sB += __shfl_xor_sync(0xffffffffu, sB, m);
            qB += __shfl_xor_sync(0xffffffffu, qB, m);
        }
        if (cq == 0) {
            int rowA = warp_m * 32 + mt * 16 + r;
            red[rowA * 2 + warp_n] = make_float2(sA, qA);
            red[(rowA + 8) * 2 + warp_n] = make_float2(sB, qB);
        }
    }
    __syncthreads();

    float muv[2][2], rsv[2][2];
#pragma unroll
    for (int mt = 0; mt < 2; mt++)
#pragma unroll
        for (int hb = 0; hb < 2; hb++) {
            int row = warp_m * 32 + mt * 16 + r + hb * 8;
            float2 p0 = red[row * 2 + 0], p1 = red[row * 2 + 1];
            float s = p0.x + p1.x, q = p0.y + p1.y;
            float mu = s * (1.0f / 128.0f);
            float var = q * (1.0f / 128.0f) - mu * mu;
            muv[mt][hb] = mu;
            rsv[mt][hb] = rsqrtf(var + LN_EPS);
        }

#pragma unroll
    for (int mt = 0; mt < 2; mt++) {
#pragma unroll
        for (int nt = 0; nt < 8; nt++) {
            int col = warp_n * 64 + nt * 8 + 2 * cq;
            int c2 = warp_n * 32 + nt * 4 + cq;
            float g0 = sgam[col], g1 = sgam[col + 1];
            float b0 = sbet[col], b1 = sbet[col + 1];
            int rowA = warp_m * 32 + mt * 16 + r;
            {
                float x0 = tanhf((C[mt][nt][0] - muv[mt][0]) * rsv[mt][0] * g0 + b0);
                float x1 = tanhf((C[mt][nt][1] - muv[mt][0]) * rsv[mt][0] * g1 + b1);
                __nv_bfloat16 h0 = __float2bfloat16(x0);
                __nv_bfloat16 h1 = __float2bfloat16(x1);
                __nv_bfloat162 hv; hv.x = h0; hv.y = h1;
                __nv_bfloat162 lv;
                lv.x = __float2bfloat16(x0 - __bfloat162float(h0));
                lv.y = __float2bfloat16(x1 - __bfloat162float(h1));
                Xh2[rowA * 68 + c2] = hv;
                Xl2[rowA * 68 + c2] = lv;
            }
            {
                float x0 = tanhf((C[mt][nt][2] - muv[mt][1]) * rsv[mt][1] * g0 + b0);
                float x1 = tanhf((C[mt][nt][3] - muv[mt][1]) * rsv[mt][1] * g1 + b1);
                __nv_bfloat16 h0 = __float2bfloat16(x0);
                __nv_bfloat16 h1 = __float2bfloat16(x1);
                __nv_bfloat162 hv; hv.x = h0; hv.y = h1;
                __nv_bfloat162 lv;
                lv.x = __float2bfloat16(x0 - __bfloat162float(h0));
                lv.y = __float2bfloat16(x1 - __bfloat162float(h1));
                Xh2[(rowA + 8) * 68 + c2] = hv;
                Xl2[(rowA + 8) * 68 + c2] = lv;
            }
        }
    }
    __syncthreads();

    // ================= phase 2: gi = X @ Wih^T + b =================
    for (int pass = 0; pass < 8; pass++) {
        float D[2][4][4];
#pragma unroll
        for (int mt = 0; mt < 2; mt++)
#pragma unroll
            for (int nt = 0; nt < 4; nt++)
#pragma unroll
                for (int v = 0; v < 4; v++) D[mt][nt][v] = 0.0f;

#pragma unroll
        for (int k = 0; k < 8; k++) {
            uint32_t ah[2][4], al[2][4];
#pragma unroll
            for (int mt = 0; mt < 2; mt++) {
                LDSM_X4(ah[mt][0], ah[mt][1], ah[mt][2], ah[mt][3], aXh[mt] + k * 32);
                LDSM_X4(al[mt][0], al[mt][1], al[mt][2], al[mt][3], aXl[mt] + k * 32);
            }
#pragma unroll
            for (int nt = 0; nt < 4; nt++) {
                int n = pass * 64 + warp_n * 32 + nt * 8 + r;
                uint4 bv = g_WihP[(n * 8 + k) * 4 + cq];
#pragma unroll
                for (int mt = 0; mt < 2; mt++) {
                    MMA_BF16(D[mt][nt], ah[mt][0], ah[mt][1], ah[mt][2], ah[mt][3], bv.x, bv.y);
                    MMA_BF16(D[mt][nt], ah[mt][0], ah[mt][1], ah[mt][2], ah[mt][3], bv.z, bv.w);
                    MMA_BF16(D[mt][nt], al[mt][0], al[mt][1], al[mt][2], al[mt][3], bv.x, bv.y);
                }
            }
        }
#pragma unroll
        for (int mt = 0; mt < 2; mt++) {
#pragma unroll
            for (int nt = 0; nt < 4; nt++) {
                int col = pass * 64 + warp_n * 32 + nt * 8 + 2 * cq;
                float2 bb = *(const float2*)&sbias[col];
                int rowA = warp_m * 32 + mt * 16 + r;
                if (base + rowA < nrows) {
                    float2 o = make_float2(D[mt][nt][0] + bb.x, D[mt][nt][1] + bb.y);
                    *(float2*)&g_gi[(size_t)srow[rowA] * G4 + col] = o;
                }
                int rowB = rowA + 8;
                if (base + rowB < nrows) {
                    float2 o = make_float2(D[mt][nt][2] + bb.x, D[mt][nt][3] + bb.y);
                    *(float2*)&g_gi[(size_t)srow[rowB] * G4 + col] = o;
                }
            }
        }
    }
}

// ---------------- kernel 2: LSTM recurrence v2 (unchanged from R11) ----------------
__global__ void __launch_bounds__(256, 2) k_lstm(const int* __restrict__ lens) {
    __shared__ float hs[128 * 36];
    __shared__ int ln_s[32];
    __shared__ int sp_s[32];
    __shared__ int maxlen_s;

    const int tid = threadIdx.x;
    const int lane = tid & 31, wid = tid >> 5;
    const int pg = wid >> 2;
    const int cg = wid & 3;
    const int c = cg * 32 + lane;
    const int p0 = pg * 16;
    const int bid = blockIdx.x;
    const int gidx = (bid < 148) ? bid : (403 - bid);
    const int n0 = gidx * 32;

#pragma unroll
    for (int s = 0; s < 18; s++) {
        int idx = tid + s * 256;
        if (idx < 128 * 36) hs[idx] = 0.0f;
    }
    if (tid < 32) {
        int pid = g_perm[n0 + tid];
        sp_s[tid] = pid;
        int l = lens[pid];
        ln_s[tid] = l;
#pragma unroll
        for (int m = 16; m >= 1; m >>= 1) l = max(l, __shfl_xor_sync(0xffffffffu, l, m));
        if (tid == 0) maxlen_s = l;
    }
    __syncthreads();

    int wmax = 0;
#pragma unroll
    for (int i = 0; i < 16; i++) wmax = max(wmax, ln_s[p0 + i]);
    const int blkmax = maxlen_s;

    float c_reg[16];
#pragma unroll
    for (int i = 0; i < 16; i++) c_reg[i] = 0.0f;

    for (int t = 0; t < blkmax; t++) {
        ull acc[8][4];
#pragma unroll
        for (int pp = 0; pp < 8; pp++)
#pragma unroll
            for (int g = 0; g < 4; g++) acc[pp][g] = 0ull;

        const bool active = (t < wmax);
        if (active) {
#pragma unroll 8
            for (int kk = 0; kk < 128; kk++) {
                const float* hrow = &hs[kk * 36 + p0];
                ulonglong2 a01 = *(const ulonglong2*)(hrow);
                ulonglong2 a23 = *(const ulonglong2*)(hrow + 4);
                ulonglong2 a45 = *(const ulonglong2*)(hrow + 8);
                ulonglong2 a67 = *(const ulonglong2*)(hrow + 12);
                ull A[8] = {a01.x, a01.y, a23.x, a23.y, a45.x, a45.y, a67.x, a67.y};
                const float* wrow = &g_WhhT[kk * G4 + c];
                float b0 = wrow[0];
                float b1 = wrow[128];
                float b2 = wrow[256];
                float b3 = wrow[384];
                ull B[4] = {pack2(b0, b0), pack2(b1, b1), pack2(b2, b2), pack2(b3, b3)};
#pragma unroll
                for (int pp = 0; pp < 8; pp++) {
                    acc[pp][0] = fma2(A[pp], B[0], acc[pp][0]);
                    acc[pp][1] = fma2(A[pp], B[1], acc[pp][1]);
                    acc[pp][2] = fma2(A[pp], B[2], acc[pp][2]);
                    acc[pp][3] = fma2(A[pp], B[3], acc[pp][3]);
                }
            }
        }
        __syncthreads();

        if (active) {
#pragma unroll
            for (int pp = 0; pp < 8; pp++) {
                int pa = p0 + 2 * pp, pb = pa + 1;
                bool la = (t < ln_s[pa]);
                bool lb = (t < ln_s[pb]);
                if (la | lb) {
                    float2 vi = unpack2(acc[pp][0]);
                    float2 vf = unpack2(acc[pp][1]);
                    float2 vg = unpack2(acc[pp][2]);
                    float2 vo = unpack2(acc[pp][3]);
                    float ha = 0.0f, hb = 0.0f;
                    if (la) {
                        size_t row = ((size_t)sp_s[pa] * LMAX + t) * G4 + c;
                        float xi = g_gi[row] + vi.x;
                        float xf = g_gi[row + 128] + vf.x;
                        float xg = g_gi[row + 256] + vg.x;
                        float xo = g_gi[row + 384] + vo.x;
                        float cn = sigm(xf) * c_reg[2 * pp] + sigm(xi) * tanhf(xg);
                        c_reg[2 * pp] = cn;
                        ha = sigm(xo) * tanhf(cn);
                    }
                    if (lb) {
                        size_t row = ((size_t)sp_s[pb] * LMAX + t) * G4 + c;
                        float xi = g_gi[row] + vi.y;
                        float xf = g_gi[row + 128] + vf.y;
                        float xg = g_gi[row + 256] + vg.y;
                        float xo = g_gi[row + 384] + vo.y;
                        float cn = sigm(xf) * c_reg[2 * pp + 1] + sigm(xi) * tanhf(xg);
                        c_reg[2 * pp + 1] = cn;
                        hb = sigm(xo) * tanhf(cn);
                    }
                    if (la && lb) {
                        *(float2*)&hs[c * 36 + pa] = make_float2(ha, hb);
                    } else if (la) {
                        hs[c * 36 + pa] = ha;
                    } else {
                        hs[c * 36 + pb] = hb;
                    }
                }
            }
        }
        __syncthreads();
    }

#pragma unroll
    for (int s = 0; s < 16; s++) {
        int idx = tid + s * 256;
        int n = idx & 31, k = idx >> 5;
        g_h[(size_t)sp_s[n] * HDIM + k] = hs[k * 36 + n];
    }
}

// ---------------- kernel 3a: init accumulators (+ counters) ----------------
__global__ void k_init() {
    int i = blockIdx.x * blockDim.x + threadIdx.x;
    if (i < GRP * HDIM) g_wsum[i] = 0.0f;
    if (i < GRP) {
        g_gsum[i] = 0.0f;
        g_cnt[i] = 0.0f;
        g_gmax[i] = 0u;
    }
    if (i < 40) g_lcnt[i] = 0;
    if (i == 0) g_nrows = 0;
}

// ---------------- kernel 3b: attention logits + segment max ----------------
__global__ void __launch_bounds__(256) k_logits(const float* __restrict__ ap,
                                                const int* __restrict__ seg) {
    int w = threadIdx.x >> 5, lane = threadIdx.x & 31;
    int n = blockIdx.x * 8 + w;
    float s = 0.0f;
#pragma unroll
    for (int q = 0; q < 4; q++) s += g_h[n * HDIM + lane + 32 * q] * ap[lane + 32 * q];
#pragma unroll
    for (int m = 16; m >= 1; m >>= 1) s += __shfl_xor_sync(0xffffffffu, s, m);
    if (lane == 0) {
        g_logits[n] = s;
        atomicMax(&g_gmax[seg[n]], enc_f(s));
    }
}

// ---------------- kernel 3c: exp + segment sum + count ----------------
__global__ void __launch_bounds__(256) k_expsum(const int* __restrict__ seg) {
    int n = blockIdx.x * 256 + threadIdx.x;
    int g = seg[n];
    float e = expf(g_logits[n] - dec_f(g_gmax[g]));
    g_e[n] = e;
    atomicAdd(&g_gsum[g], e);
    atomicAdd(&g_cnt[g], 1.0f);
}

// ---------------- kernel 3d: weighted hidden sum per group ----------------
__global__ void __launch_bounds__(256) k_wsum(const int* __restrict__ seg) {
    int w = threadIdx.x >> 5, lane = threadIdx.x & 31;
    int n = blockIdx.x * 8 + w;
    float e = g_e[n];
    int g = seg[n];
#pragma unroll
    for (int q = 0; q < 4; q++)
        atomicAdd(&g_wsum[g * HDIM + lane + 32 * q], e * g_h[n * HDIM + lane + 32 * q]);
}

// ---------------- kernel 4: head ----------------
__global__ void __launch_bounds__(256) k_head(const float* __restrict__ W_out,
                                              const float* __restrict__ W_cls,
                                              const float* __restrict__ ap,
                                              float* __restrict__ out,
                                              int out_size) {
    __shared__ float cs[16 * 128];
    __shared__ float cvs[16 * 128];
    const int tid = threadIdx.x;
    const int g0 = blockIdx.x * 16;
    const bool full = (out_size >= 2048 + GRP * HDIM + HDIM);

#pragma unroll
    for (int s = 0; s < 8; s++) {
        int idx = tid + s * 256;
        int gg = idx >> 7, k = idx & 127;
        int gi = g0 + gg;
        cs[gg * 128 + k] = g_wsum[gi * HDIM + k] / (g_gsum[gi] * g_cnt[gi]);
    }
    __syncthreads();

    int row = tid >> 4;
    int c0 = (tid & 15) * 8;
    float acc[8];
#pragma unroll
    for (int j = 0; j < 8; j++) acc[j] = 0.0f;
    for (int k = 0; k < 128; k++) {
        float a = cs[row * 128 + k];
#pragma unroll
        for (int j = 0; j < 8; j++) acc[j] += a * W_out[(c0 + j) * 128 + k];
    }
#pragma unroll
    for (int j = 0; j < 8; j++) {
        cvs[row * 128 + c0 + j] = acc[j];
        if (full) out[2048 + (g0 + row) * 128 + c0 + j] = acc[j];
    }
    __syncthreads();

    if (tid < 32) {
        int rr = tid >> 1, cc = tid & 1;
        float s = 0.0f;
        for (int k = 0; k < 128; k++) s += cvs[rr * 128 + k] * W_cls[cc * 128 + k];
        out[(g0 + rr) * 2 + cc] = s;
    }
    if (full && blockIdx.x == 0 && tid < 128) out[2048 + GRP * HDIM + tid] = ap[tid];
}

// ---------------- launch ----------------
extern "C" void kernel_launch(void* const* d_in, const int* in_sizes, int n_in,
                              void* d_out, int out_size) {
    const float* inputs = (const float*)d_in[0];
    const int* lens     = (const int*)d_in[1];
    const int* seg      = (const int*)d_in[2];
    const float* W_in   = (const float*)d_in[3];
    const float* gamma  = (const float*)d_in[4];
    const float* beta   = (const float*)d_in[5];
    const float* Wih    = (const float*)d_in[6];
    const float* Whh    = (const float*)d_in[7];
    const float* bih    = (const float*)d_in[8];
    const float* bhh    = (const float*)d_in[9];
    const float* ap     = (const float*)d_in[10];
    const float* W_out  = (const float*)d_in[11];
    const float* W_cls  = (const float*)d_in[12];
    float* out = (float*)d_out;

    const int fp_smem = FP_SMEM_B32 * 4;   // 112128 B
    cudaFuncSetAttribute(k_fp, cudaFuncAttributeMaxDynamicSharedMemorySize, fp_smem);

    k_init<<<(GRP * HDIM + 255) / 256, 256>>>();
    k_rowlist<<<NPATH / 256, 256>>>(lens);
    k_prep<<<256, 256>>>(Whh, Wih, W_in);
    k_prep2<<<96, 256>>>();
    k_fp<<<RTOT / 128, 256, fp_smem>>>(inputs, gamma, beta, bih, bhh);
    k_hist<<<NPATH / 256, 256>>>(lens);
    k_scan<<<1, 32>>>();
    k_scatter<<<NPATH / 256, 256>>>(lens);
    k_lstm<<<NPATH / 32, 256>>>(lens);
    k_logits<<<NPATH / 8, 256>>>(ap, seg);
    k_expsum<<<NPATH / 256, 256>>>(seg);
    k_wsum<<<NPATH / 8, 256>>>(seg);
    k_head<<<GRP / 16, 256>>>(W_out, W_cls, ap, out, out_size);
}

// round 15
// speedup vs baseline: 2.7202x; 1.7367x over previous
#include <cuda_runtime.h>
#include <cuda_bf16.h>
#include <cstdint>

#define NPATH 8192
#define LMAX 32
#define DIN 256
#define EDIM 128
#define HDIM 128
#define G4 512
#define GRP 1024
#define RTOT (NPATH*LMAX)
#define LN_EPS 1e-5f

typedef unsigned long long ull;

// ---------------- device scratch (static, no allocation) ----------------
__device__ float g_gi[(size_t)RTOT*G4]; // 512 MB
__device__ uint4 g_WinP[EDIM*16*4];     // [(n*16+kf)*4+cq] = {bh0,bh1,bl0,bl1}
__device__ uint4 g_WihP[G4*8*4];        // [(n*8+kf)*4+cq]
__device__ uint4 g_WhhP[G4*8*4];        // [(n*8+kf)*4+cq]
__device__ float g_h[NPATH*HDIM];
__device__ float g_logits[NPATH];
__device__ float g_e[NPATH];
__device__ unsigned g_gmax[GRP];
__device__ float g_gsum[GRP];
__device__ float g_cnt[GRP];
__device__ float g_wsum[GRP*HDIM];
__device__ int g_lcnt[40];
__device__ int g_lstart[40];
__device__ int g_perm[NPATH];
__device__ int g_nrows;
__device__ int g_rows[RTOT];

// ---------------- fast activations (clamped, ~1e-6 rel err) ----------------
__device__ __forceinline__ float sigm_f(float x) {
    x = fmaxf(fminf(x, 30.0f), -30.0f);
    return __fdividef(1.0f, 1.0f + __expf(-x));
}
__device__ __forceinline__ float tanh_f(float x) {
    x = fmaxf(fminf(x, 15.0f), -15.0f);
    float e = __expf(-2.0f * x);
    return __fdividef(1.0f - e, 1.0f + e);
}

__device__ __forceinline__ unsigned enc_f(float f) {
    unsigned u = __float_as_uint(f);
    return (u & 0x80000000u) ? ~u : (u | 0x80000000u);
}
__device__ __forceinline__ float dec_f(unsigned k) {
    return (k & 0x80000000u) ? __uint_as_float(k ^ 0x80000000u) : __uint_as_float(~k);
}

// ---------------- mma / ldmatrix helpers ----------------
#define MMA_BF16(Cr, a0, a1, a2, a3, b0, b1) \
    asm volatile("mma.sync.aligned.m16n8k16.row.col.f32.bf16.bf16.f32 " \
        "{%0,%1,%2,%3}, {%4,%5,%6,%7}, {%8,%9}, {%0,%1,%2,%3};" \
        : "+f"((Cr)[0]), "+f"((Cr)[1]), "+f"((Cr)[2]), "+f"((Cr)[3]) \
        : "r"(a0), "r"(a1), "r"(a2), "r"(a3), "r"(b0), "r"(b1))

#define LDSM_X4(r0, r1, r2, r3, a) \
    asm volatile("ldmatrix.sync.aligned.m8n8.x4.shared.b16 {%0,%1,%2,%3}, [%4];" \
        : "=r"(r0), "=r"(r1), "=r"(r2), "=r"(r3) : "r"(a))

__device__ __forceinline__ uint32_t smem_u32(const void* p) {
    uint32_t a;
    asm("{ .reg .u64 t; cvta.to.shared.u64 t, %1; cvt.u32.u64 %0, t; }" : "=r"(a) : "l"(p));
    return a;
}
__device__ __forceinline__ uint32_t bf2_pack(float x, float y) {
    __nv_bfloat162 v;
    v.x = __float2bfloat16(x);
    v.y = __float2bfloat16(y);
    return *(uint32_t*)&v;
}

// ---------------- sort kernels ----------------
__global__ void k_hist(const int* __restrict__ lens) {
    int n = blockIdx.x * 256 + threadIdx.x;
    if (n < NPATH) atomicAdd(&g_lcnt[lens[n]], 1);
}
__global__ void k_scan() {
    if (threadIdx.x == 0 && blockIdx.x == 0) {
        int run = 0;
        for (int l = LMAX; l >= 1; l--) { g_lstart[l] = run; run += g_lcnt[l]; }
    }
}
__global__ void k_scatter(const int* __restrict__ lens) {
    int n = blockIdx.x * 256 + threadIdx.x;
    if (n < NPATH) {
        int pos = atomicAdd(&g_lstart[lens[n]], 1);
        g_perm[pos] = n;
    }
}
__global__ void k_rowlist(const int* __restrict__ lens) {
    int n = blockIdx.x * 256 + threadIdx.x;
    if (n < NPATH) {
        int l = lens[n];
        int pos = atomicAdd(&g_nrows, l);
        int base = n * LMAX;
        for (int t = 0; t < l; t++) g_rows[pos + t] = base + t;
    }
}

// ---------------- kernel 0: fragment-pack all weights (fp32 -> bf16 hi/lo uint4) ----------------
__device__ __forceinline__ uint4 pack_frag(const float* __restrict__ W, int e) {
    float a0 = W[e], a1 = W[e + 1], a2 = W[e + 8], a3 = W[e + 9];
    __nv_bfloat16 h0 = __float2bfloat16(a0), h1 = __float2bfloat16(a1);
    __nv_bfloat16 h2 = __float2bfloat16(a2), h3 = __float2bfloat16(a3);
    uint4 v;
    v.x = bf2_pack(a0, a1);
    v.y = bf2_pack(a2, a3);
    v.z = bf2_pack(a0 - __bfloat162float(h0), a1 - __bfloat162float(h1));
    v.w = bf2_pack(a2 - __bfloat162float(h2), a3 - __bfloat162float(h3));
    return v;
}
__global__ void __launch_bounds__(256) k_prep(const float* __restrict__ W_in,
                                              const float* __restrict__ Wih,
                                              const float* __restrict__ Whh) {
    int idx = blockIdx.x * 256 + threadIdx.x;   // 40960 total
    if (idx < 8192) {
        int cq = idx & 3, kf = (idx >> 2) & 15, n = idx >> 6;
        g_WinP[idx] = pack_frag(W_in, n * DIN + kf * 16 + 2 * cq);
    } else if (idx < 24576) {
        int i2 = idx - 8192;
        int cq = i2 & 3, kf = (i2 >> 2) & 7, n = i2 >> 5;
        g_WihP[i2] = pack_frag(Wih, n * HDIM + kf * 16 + 2 * cq);
    } else if (idx < 40960) {
        int i2 = idx - 24576;
        int cq = i2 & 3, kf = (i2 >> 2) & 7, n = i2 >> 5;
        g_WhhP[i2] = pack_frag(Whh, n * HDIM + kf * 16 + 2 * cq);
    }
}

// smem offsets (b32 units) for k_fp
#define OFF_AH   0
#define OFF_AL   4608
#define OFF_XH   9216
#define OFF_XL   17920
#define OFF_RED  26624
#define OFF_GAM  27136
#define OFF_BET  27264
#define OFF_BIAS 27392
#define OFF_SROW 27904
#define FP_SMEM_B32 28032

// ---------------- kernel 1: mma-based fused projection+LN+tanh + gate GEMM ----------------
__global__ void __launch_bounds__(256, 2) k_fp(const float* __restrict__ inp,
                                               const float* __restrict__ gamma,
                                               const float* __restrict__ beta,
                                               const float* __restrict__ bih,
                                               const float* __restrict__ bhh) {
    extern __shared__ uint32_t s32[];
    __nv_bfloat16* Ah16 = (__nv_bfloat16*)(s32 + OFF_AH);
    __nv_bfloat16* Al16 = (__nv_bfloat16*)(s32 + OFF_AL);
    __nv_bfloat162* Xh2 = (__nv_bfloat162*)(s32 + OFF_XH);
    __nv_bfloat162* Xl2 = (__nv_bfloat162*)(s32 + OFF_XL);
    float2* red = (float2*)(s32 + OFF_RED);
    float* sgam = (float*)(s32 + OFF_GAM);
    float* sbet = (float*)(s32 + OFF_BET);
    float* sbias = (float*)(s32 + OFF_BIAS);
    int* srow = (int*)(s32 + OFF_SROW);

    const int tid = threadIdx.x;
    const int lane = tid & 31, wid = tid >> 5;
    const int warp_m = wid & 3, warp_n = wid >> 2;
    const int r = lane >> 2, cq = lane & 3;
    const int base = blockIdx.x * 128;
    const int nrows = g_nrows;
    if (base >= nrows) return;

    const int Lrow = ((lane >> 3) & 1) * 8 + (lane & 7);
    const int Lk8 = (lane >> 4) * 8;

    if (tid < 128) {
        srow[tid] = (base + tid < nrows) ? g_rows[base + tid] : g_rows[base];
        sgam[tid] = gamma[tid];
        sbet[tid] = beta[tid];
    }
    sbias[tid] = bih[tid] + bhh[tid];
    sbias[tid + 256] = bih[tid + 256] + bhh[tid + 256];
    __syncthreads();

    uint32_t aAh[2], aAl[2], aXh[2], aXl[2];
#pragma unroll
    for (int mt = 0; mt < 2; mt++) {
        int row = warp_m * 32 + mt * 16 + Lrow;
        aAh[mt] = smem_u32(Ah16) + (row * 72 + Lk8) * 2;
        aAl[mt] = smem_u32(Al16) + (row * 72 + Lk8) * 2;
        aXh[mt] = smem_u32(Xh2) + row * 68 * 4 + Lk8 * 2;
        aXl[mt] = smem_u32(Xl2) + row * 68 * 4 + Lk8 * 2;
    }

    // phase 1
    float C[2][8][4];
#pragma unroll
    for (int mt = 0; mt < 2; mt++)
#pragma unroll
        for (int nt = 0; nt < 8; nt++)
#pragma unroll
            for (int v = 0; v < 4; v++) C[mt][nt][v] = 0.0f;

    for (int ks = 0; ks < 4; ks++) {
        __syncthreads();
#pragma unroll
        for (int s = 0; s < 32; s++) {
            int idx = tid + s * 256;
            int row = idx >> 6, c = idx & 63;
            float v = inp[(size_t)srow[row] * DIN + ks * 64 + c];
            __nv_bfloat16 h = __float2bfloat16(v);
            Ah16[row * 72 + c] = h;
            Al16[row * 72 + c] = __float2bfloat16(v - __bfloat162float(h));
        }
        __syncthreads();
#pragma unroll
        for (int k4 = 0; k4 < 4; k4++) {
            uint32_t ah[2][4], al[2][4];
#pragma unroll
            for (int mt = 0; mt < 2; mt++) {
                LDSM_X4(ah[mt][0], ah[mt][1], ah[mt][2], ah[mt][3], aAh[mt] + k4 * 32);
                LDSM_X4(al[mt][0], al[mt][1], al[mt][2], al[mt][3], aAl[mt] + k4 * 32);
            }
            const int kf = ks * 4 + k4;
#pragma unroll
            for (int nt = 0; nt < 8; nt++) {
                int n = warp_n * 64 + nt * 8 + r;
                uint4 bv = g_WinP[(n * 16 + kf) * 4 + cq];
#pragma unroll
                for (int mt = 0; mt < 2; mt++) {
                    MMA_BF16(C[mt][nt], ah[mt][0], ah[mt][1], ah[mt][2], ah[mt][3], bv.x, bv.y);
                    MMA_BF16(C[mt][nt], ah[mt][0], ah[mt][1], ah[mt][2], ah[mt][3], bv.z, bv.w);
                    MMA_BF16(C[mt][nt], al[mt][0], al[mt][1], al[mt][2], al[mt][3], bv.x, bv.y);
                }
            }
        }
    }

    // LN + tanh epilogue -> Xh/Xl
    __syncthreads();
#pragma unroll
    for (int mt = 0; mt < 2; mt++) {
        float sA = 0.f, qA = 0.f, sB = 0.f, qB = 0.f;
#pragma unroll
        for (int nt = 0; nt < 8; nt++) {
            sA += C[mt][nt][0] + C[mt][nt][1];
            qA += C[mt][nt][0] * C[mt][nt][0] + C[mt][nt][1] * C[mt][nt][1];
            sB += C[mt][nt][2] + C[mt][nt][3];
            qB += C[mt][nt][2] * C[mt][nt][2] + C[mt][nt][3] * C[mt][nt][3];
        }
#pragma unroll
        for (int m = 1; m <= 2; m <<= 1) {
            sA += __shfl_xor_sync(0xffffffffu, sA, m);
            qA += __shfl_xor_sync(0xffffffffu, qA, m);
            sB += __shfl_xor_sync(0xffffffffu, sB, m);
            qB += __shfl_xor_sync(0xffffffffu, qB, m);
        }
        if (cq == 0) {
            int rowA = warp_m * 32 + mt * 16 + r;
            red[rowA * 2 + warp_n] = make_float2(sA, qA);
            red[(rowA + 8) * 2 + warp_n] = make_float2(sB, qB);
        }
    }
    __syncthreads();

    float muv[2][2], rsv[2][2];
#pragma unroll
    for (int mt = 0; mt < 2; mt++)
#pragma unroll
        for (int hb = 0; hb < 2; hb++) {
            int row = warp_m * 32 + mt * 16 + r + hb * 8;
            float2 p0 = red[row * 2 + 0], p1 = red[row * 2 + 1];
            float s = p0.x + p1.x, q = p0.y + p1.y;
            float mu = s * (1.0f / 128.0f);
            float var = q * (1.0f / 128.0f) - mu * mu;
            muv[mt][hb] = mu;
            rsv[mt][hb] = rsqrtf(var + LN_EPS);
        }

#pragma unroll
    for (int mt = 0; mt < 2; mt++) {
#pragma unroll
        for (int nt = 0; nt < 8; nt++) {
            int col = warp_n * 64 + nt * 8 + 2 * cq;
            int c2 = warp_n * 32 + nt * 4 + cq;
            float g0 = sgam[col], g1 = sgam[col + 1];
            float b0 = sbet[col], b1 = sbet[col + 1];
            int rowA = warp_m * 32 + mt * 16 + r;
#pragma unroll
            for (int hb = 0; hb < 2; hb++) {
                float x0 = tanh_f((C[mt][nt][2 * hb] - muv[mt][hb]) * rsv[mt][hb] * g0 + b0);
                float x1 = tanh_f((C[mt][nt][2 * hb + 1] - muv[mt][hb]) * rsv[mt][hb] * g1 + b1);
                __nv_bfloat16 h0 = __float2bfloat16(x0);
                __nv_bfloat16 h1 = __float2bfloat16(x1);
                __nv_bfloat162 hv; hv.x = h0; hv.y = h1;
                __nv_bfloat162 lv;
                lv.x = __float2bfloat16(x0 - __bfloat162float(h0));
                lv.y = __float2bfloat16(x1 - __bfloat162float(h1));
                Xh2[(rowA + hb * 8) * 68 + c2] = hv;
                Xl2[(rowA + hb * 8) * 68 + c2] = lv;
            }
        }
    }
    __syncthreads();

    // phase 2
    for (int pass = 0; pass < 8; pass++) {
        float D[2][4][4];
#pragma unroll
        for (int mt = 0; mt < 2; mt++)
#pragma unroll
            for (int nt = 0; nt < 4; nt++)
#pragma unroll
                for (int v = 0; v < 4; v++) D[mt][nt][v] = 0.0f;

#pragma unroll
        for (int k = 0; k < 8; k++) {
            uint32_t ah[2][4], al[2][4];
#pragma unroll
            for (int mt = 0; mt < 2; mt++) {
                LDSM_X4(ah[mt][0], ah[mt][1], ah[mt][2], ah[mt][3], aXh[mt] + k * 32);
                LDSM_X4(al[mt][0], al[mt][1], al[mt][2], al[mt][3], aXl[mt] + k * 32);
            }
#pragma unroll
            for (int nt = 0; nt < 4; nt++) {
                int n = pass * 64 + warp_n * 32 + nt * 8 + r;
                uint4 bv = g_WihP[(n * 8 + k) * 4 + cq];
#pragma unroll
                for (int mt = 0; mt < 2; mt++) {
                    MMA_BF16(D[mt][nt], ah[mt][0], ah[mt][1], ah[mt][2], ah[mt][3], bv.x, bv.y);
                    MMA_BF16(D[mt][nt], ah[mt][0], ah[mt][1], ah[mt][2], ah[mt][3], bv.z, bv.w);
                    MMA_BF16(D[mt][nt], al[mt][0], al[mt][1], al[mt][2], al[mt][3], bv.x, bv.y);
                }
            }
        }
#pragma unroll
        for (int mt = 0; mt < 2; mt++) {
#pragma unroll
            for (int nt = 0; nt < 4; nt++) {
                int col = pass * 64 + warp_n * 32 + nt * 8 + 2 * cq;
                float2 bb = *(const float2*)&sbias[col];
                int rowA = warp_m * 32 + mt * 16 + r;
                if (base + rowA < nrows) {
                    float2 o = make_float2(D[mt][nt][0] + bb.x, D[mt][nt][1] + bb.y);
                    *(float2*)&g_gi[(size_t)srow[rowA] * G4 + col] = o;
                }
                int rowB = rowA + 8;
                if (base + rowB < nrows) {
                    float2 o = make_float2(D[mt][nt][2] + bb.x, D[mt][nt][3] + bb.y);
                    *(float2*)&g_gi[(size_t)srow[rowB] * G4 + col] = o;
                }
            }
        }
    }
}

// ---------------- kernel 2: LSTM recurrence v4b — HMMA, 16 paths/block ----------------
// Stride fixed: h rows are 136 bf16 (128 cols + 8 pad), matching k_fp's X layout.
// All gate columns computed BEFORE any h write; one sync separates reads/writes.
#define HSTRIDE 136
__global__ void __launch_bounds__(256) k_lstm(const int* __restrict__ lens) {
    __shared__ __nv_bfloat16 Hh[16 * HSTRIDE];
    __shared__ __nv_bfloat16 Hl[16 * HSTRIDE];
    __shared__ int ln_s[16];
    __shared__ int sp_s[16];
    __shared__ int maxlen_s;

    const int tid = threadIdx.x;
    const int lane = tid & 31, wid = tid >> 5;
    const int s = wid * 16;
    const int r = lane >> 2, cq = lane & 3;
    const int Lrow = ((lane >> 3) & 1) * 8 + (lane & 7);
    const int Lk8 = (lane >> 4) * 8;
    const int n0 = blockIdx.x * 16;

#pragma unroll
    for (int q = 0; q < 5; q++) {
        int idx = tid + q * 256;
        if (idx < 16 * HSTRIDE / 2) {
            ((uint32_t*)Hh)[idx] = 0u;
            ((uint32_t*)Hl)[idx] = 0u;
        }
    }
    if (tid < 16) {
        int pid = g_perm[n0 + tid];
        sp_s[tid] = pid;
        ln_s[tid] = lens[pid];
    }
    __syncthreads();
    if (tid == 0) {
        int m = 0;
#pragma unroll
        for (int i = 0; i < 16; i++) m = max(m, ln_s[i]);
        maxlen_s = m;
    }
    __syncthreads();

    int mylen[2], mypid[2];
#pragma unroll
    for (int rr = 0; rr < 2; rr++) {
        int pI = rr * 8 + r;
        mylen[rr] = ln_s[pI];
        mypid[rr] = sp_s[pI];
    }
    const int blkmax = maxlen_s;

    const uint32_t aH = smem_u32(Hh) + (Lrow * HSTRIDE + Lk8) * 2;
    const uint32_t aL = smem_u32(Hl) + (Lrow * HSTRIDE + Lk8) * 2;

    float cst[2][2][2];   // [rr][j][col01]
#pragma unroll
    for (int a = 0; a < 2; a++)
#pragma unroll
        for (int b = 0; b < 2; b++) { cst[a][b][0] = 0.f; cst[a][b][1] = 0.f; }

    for (int t = 0; t < blkmax; t++) {
        float C[2][4][4];   // [j][gate][v]
#pragma unroll
        for (int j = 0; j < 2; j++)
#pragma unroll
            for (int q = 0; q < 4; q++)
#pragma unroll
                for (int v = 0; v < 4; v++) C[j][q][v] = 0.0f;

#pragma unroll
        for (int kf = 0; kf < 8; kf++) {
            uint32_t ah[4], al[4];
            LDSM_X4(ah[0], ah[1], ah[2], ah[3], aH + kf * 32);
            LDSM_X4(al[0], al[1], al[2], al[3], aL + kf * 32);
#pragma unroll
            for (int j = 0; j < 2; j++) {
#pragma unroll
                for (int q = 0; q < 4; q++) {
                    int n = q * 128 + s + j * 8 + r;
                    uint4 bv = g_WhhP[(n * 8 + kf) * 4 + cq];
                    MMA_BF16(C[j][q], ah[0], ah[1], ah[2], ah[3], bv.x, bv.y);
                    MMA_BF16(C[j][q], ah[0], ah[1], ah[2], ah[3], bv.z, bv.w);
                    MMA_BF16(C[j][q], al[0], al[1], al[2], al[3], bv.x, bv.y);
                }
            }
        }
        __syncthreads();   // ALL h reads complete before any h write

#pragma unroll
        for (int j = 0; j < 2; j++) {
            const int colg = s + j * 8 + 2 * cq;
#pragma unroll
            for (int rr = 0; rr < 2; rr++) {
                if (t < mylen[rr]) {
                    size_t row = ((size_t)mypid[rr] * LMAX + t) * G4 + colg;
                    float2 gi = *(const float2*)&g_gi[row];
                    float2 gf = *(const float2*)&g_gi[row + 128];
                    float2 gg = *(const float2*)&g_gi[row + 256];
                    float2 go = *(const float2*)&g_gi[row + 384];
                    int v0 = rr * 2;
                    float xi0 = gi.x + C[j][0][v0], xi1 = gi.y + C[j][0][v0 + 1];
                    float xf0 = gf.x + C[j][1][v0], xf1 = gf.y + C[j][1][v0 + 1];
                    float xg0 = gg.x + C[j][2][v0], xg1 = gg.y + C[j][2][v0 + 1];
                    float xo0 = go.x + C[j][3][v0], xo1 = go.y + C[j][3][v0 + 1];
                    float cn0 = sigm_f(xf0) * cst[rr][j][0] + sigm_f(xi0) * tanh_f(xg0);
                    float cn1 = sigm_f(xf1) * cst[rr][j][1] + sigm_f(xi1) * tanh_f(xg1);
                    cst[rr][j][0] = cn0;
                    cst[rr][j][1] = cn1;
                    float h0 = sigm_f(xo0) * tanh_f(cn0);
                    float h1 = sigm_f(xo1) * tanh_f(cn1);
                    __nv_bfloat16 b0 = __float2bfloat16(h0);
                    __nv_bfloat16 b1 = __float2bfloat16(h1);
                    __nv_bfloat162 hv; hv.x = b0; hv.y = b1;
                    __nv_bfloat162 lv;
                    lv.x = __float2bfloat16(h0 - __bfloat162float(b0));
                    lv.y = __float2bfloat16(h1 - __bfloat162float(b1));
                    int pI = rr * 8 + r;
                    *(__nv_bfloat162*)&Hh[pI * HSTRIDE + colg] = hv;
                    *(__nv_bfloat162*)&Hl[pI * HSTRIDE + colg] = lv;
                }
            }
        }
        __syncthreads();
    }

    // final h: g_h[pid][k] = hi + lo
#pragma unroll
    for (int q = 0; q < 8; q++) {
        int idx = tid + q * 256;
        int n = idx >> 7, k = idx & 127;
        g_h[(size_t)sp_s[n] * HDIM + k] =
            __bfloat162float(Hh[n * HSTRIDE + k]) + __bfloat162float(Hl[n * HSTRIDE + k]);
    }
}

// ---------------- kernel 3a: init accumulators (+ counters) ----------------
__global__ void k_init() {
    int i = blockIdx.x * blockDim.x + threadIdx.x;
    if (i < GRP * HDIM) g_wsum[i] = 0.0f;
    if (i < GRP) {
        g_gsum[i] = 0.0f;
        g_cnt[i] = 0.0f;
        g_gmax[i] = 0u;
    }
    if (i < 40) g_lcnt[i] = 0;
    if (i == 0) g_nrows = 0;
}

// ---------------- kernel 3b: attention logits + segment max ----------------
__global__ void __launch_bounds__(256) k_logits(const float* __restrict__ ap,
                                                const int* __restrict__ seg) {
    int w = threadIdx.x >> 5, lane = threadIdx.x & 31;
    int n = blockIdx.x * 8 + w;
    float s = 0.0f;
#pragma unroll
    for (int q = 0; q < 4; q++) s += g_h[n * HDIM + lane + 32 * q] * ap[lane + 32 * q];
#pragma unroll
    for (int m = 16; m >= 1; m >>= 1) s += __shfl_xor_sync(0xffffffffu, s, m);
    if (lane == 0) {
        g_logits[n] = s;
        atomicMax(&g_gmax[seg[n]], enc_f(s));
    }
}

// ---------------- kernel 3c: exp + segment sum + count ----------------
__global__ void __launch_bounds__(256) k_expsum(const int* __restrict__ seg) {
    int n = blockIdx.x * 256 + threadIdx.x;
    int g = seg[n];
    float e = expf(g_logits[n] - dec_f(g_gmax[g]));
    g_e[n] = e;
    atomicAdd(&g_gsum[g], e);
    atomicAdd(&g_cnt[g], 1.0f);
}

// ---------------- kernel 3d: weighted hidden sum per group ----------------
__global__ void __launch_bounds__(256) k_wsum(const int* __restrict__ seg) {
    int w = threadIdx.x >> 5, lane = threadIdx.x & 31;
    int n = blockIdx.x * 8 + w;
    float e = g_e[n];
    int g = seg[n];
#pragma unroll
    for (int q = 0; q < 4; q++)
        atomicAdd(&g_wsum[g * HDIM + lane + 32 * q], e * g_h[n * HDIM + lane + 32 * q]);
}

// ---------------- kernel 4: head ----------------
__global__ void __launch_bounds__(256) k_head(const float* __restrict__ W_out,
                                              const float* __restrict__ W_cls,
                                              const float* __restrict__ ap,
                                              float* __restrict__ out,
                                              int out_size) {
    __shared__ float cs[16 * 128];
    __shared__ float cvs[16 * 128];
    const int tid = threadIdx.x;
    const int g0 = blockIdx.x * 16;
    const bool full = (out_size >= 2048 + GRP * HDIM + HDIM);

#pragma unroll
    for (int s = 0; s < 8; s++) {
        int idx = tid + s * 256;
        int gg = idx >> 7, k = idx & 127;
        int gi = g0 + gg;
        cs[gg * 128 + k] = g_wsum[gi * HDIM + k] / (g_gsum[gi] * g_cnt[gi]);
    }
    __syncthreads();

    int row = tid >> 4;
    int c0 = (tid & 15) * 8;
    float acc[8];
#pragma unroll
    for (int j = 0; j < 8; j++) acc[j] = 0.0f;
    for (int k = 0; k < 128; k++) {
        float a = cs[row * 128 + k];
#pragma unroll
        for (int j = 0; j < 8; j++) acc[j] += a * W_out[(c0 + j) * 128 + k];
    }
#pragma unroll
    for (int j = 0; j < 8; j++) {
        cvs[row * 128 + c0 + j] = acc[j];
        if (full) out[2048 + (g0 + row) * 128 + c0 + j] = acc[j];
    }
    __syncthreads();

    if (tid < 32) {
        int rr = tid >> 1, cc = tid & 1;
        float s = 0.0f;
        for (int k = 0; k < 128; k++) s += cvs[rr * 128 + k] * W_cls[cc * 128 + k];
        out[(g0 + rr) * 2 + cc] = s;
    }
    if (full && blockIdx.x == 0 && tid < 128) out[2048 + GRP * HDIM + tid] = ap[tid];
}

// ---------------- launch ----------------
extern "C" void kernel_launch(void* const* d_in, const int* in_sizes, int n_in,
                              void* d_out, int out_size) {
    const float* inputs = (const float*)d_in[0];
    const int* lens     = (const int*)d_in[1];
    const int* seg      = (const int*)d_in[2];
    const float* W_in   = (const float*)d_in[3];
    const float* gamma  = (const float*)d_in[4];
    const float* beta   = (const float*)d_in[5];
    const float* Wih    = (const float*)d_in[6];
    const float* Whh    = (const float*)d_in[7];
    const float* bih    = (const float*)d_in[8];
    const float* bhh    = (const float*)d_in[9];
    const float* ap     = (const float*)d_in[10];
    const float* W_out  = (const float*)d_in[11];
    const float* W_cls  = (const float*)d_in[12];
    float* out = (float*)d_out;

    const int fp_smem = FP_SMEM_B32 * 4;   // 112128 B
    cudaFuncSetAttribute(k_fp, cudaFuncAttributeMaxDynamicSharedMemorySize, fp_smem);

    k_init<<<(GRP * HDIM + 255) / 256, 256>>>();
    k_rowlist<<<NPATH / 256, 256>>>(lens);
    k_prep<<<160, 256>>>(W_in, Wih, Whh);
    k_fp<<<RTOT / 128, 256, fp_smem>>>(inputs, gamma, beta, bih, bhh);
    k_hist<<<NPATH / 256, 256>>>(lens);
    k_scan<<<1, 32>>>();
    k_scatter<<<NPATH / 256, 256>>>(lens);
    k_lstm<<<NPATH / 16, 256>>>(lens);
    k_logits<<<NPATH / 8, 256>>>(ap, seg);
    k_expsum<<<NPATH / 256, 256>>>(seg);
    k_wsum<<<NPATH / 8, 256>>>(seg);
    k_head<<<GRP / 16, 256>>>(W_out, W_cls, ap, out, out_size);
}